// round 10
// baseline (speedup 1.0000x reference)
#include <cuda_runtime.h>
#include <cuda_bf16.h>
#include <cstdint>

// ---- problem constants ----
#define HDIM 300
#define HPAD 320          // padded k extent (bf16 elems)
#define HPAIR 160         // uint32 (bf16x2) pairs per row
#define BROWS 4096
#define BM 128            // batch rows per CTA
#define BH 40             // hidden units per CTA -> 8 h-blocks
#define BNC 160           // gate-columns per CTA (4*BH)
#define KPAIR 16          // k-pairs per tile (BK=32)
#define SMS 20            // smem row stride in uint32 (16 + 4 pad) -> conflict-free
#define NKT 10            // k-tiles per GEMM segment
#define NTHREADS 256
#define NW 1280           // padded row-permuted weight rows
#define PAIRSZ (BROWS * HPAIR)
#define NGRP 32           // one group per m-tile
#define GRPSZ 8           // 8 h-block CTAs per group
// dynamic smem layout (uint32 units)
#define BUFU32 11520      // AsH(2560)+AsL(2560)+BsH(3200)+BsL(3200)
#define SMEM_U32 (2 * BUFU32 + 2 * BNC)

// ---- device scratch (no allocation allowed) ----
__device__ uint32_t g_zH[PAIRSZ], g_zL[PAIRSZ];
__device__ uint32_t g_h0H[2 * PAIRSZ], g_h0L[2 * PAIRSZ];   // ping-pong layer0 h
__device__ uint32_t g_oH[2 * PAIRSZ], g_oL[2 * PAIRSZ];     // ping-pong layer1 h
__device__ uint32_t g_WH[4 * NW * HPAIR], g_WL[4 * NW * HPAIR]; // Wih0,Whh0,Wih1,Whh1
__device__ float g_c0[BROWS * HDIM], g_c1[BROWS * HDIM];
__device__ unsigned g_gc[NGRP * 32];   // per-group barrier counters (line-padded)
__device__ unsigned g_gg[NGRP * 32];   // per-group generations

extern __shared__ uint32_t dynsmem[];

// ---------- helpers ----------
__device__ __forceinline__ uint32_t pack2(__nv_bfloat16 a, __nv_bfloat16 b) {
    return (uint32_t)__bfloat16_as_ushort(a) | ((uint32_t)__bfloat16_as_ushort(b) << 16);
}
__device__ __forceinline__ void split_pack(float v0, float v1, uint32_t& hi, uint32_t& lo) {
    __nv_bfloat16 h0 = __float2bfloat16(v0);
    __nv_bfloat16 h1 = __float2bfloat16(v1);
    float r0 = v0 - __bfloat162float(h0);   // exact
    float r1 = v1 - __bfloat162float(h1);
    hi = pack2(h0, h1);
    lo = pack2(__float2bfloat16(r0), __float2bfloat16(r1));
}
__device__ __forceinline__ void cp16(uint32_t* dst, const uint32_t* src) {
    unsigned sa = (unsigned)__cvta_generic_to_shared(dst);
    asm volatile("cp.async.cg.shared.global [%0], [%1], 16;" :: "r"(sa), "l"(src));
}

// Sense-reversing barrier over the 8 CTAs of one m-tile group.
// All cross-CTA dataflow (h0/o pairs, c state) is group-local, so groups free-run.
__device__ __forceinline__ void group_barrier(int grp) {
    __threadfence();
    __syncthreads();
    if (threadIdx.x == 0) {
        unsigned* cnt = &g_gc[grp * 32];
        unsigned* gen = &g_gg[grp * 32];
        unsigned g = *(volatile unsigned*)gen;
        if (atomicAdd(cnt, 1u) == GRPSZ - 1u) {
            atomicExch(cnt, 0u);
            __threadfence();
            atomicAdd(gen, 1u);
        } else {
            while (*(volatile unsigned*)gen == g) __nanosleep(32);
        }
        __threadfence();
    }
    __syncthreads();
}

// ---------- prep kernels ----------
__global__ void prep_weights(const float* __restrict__ W0, const float* __restrict__ W1,
                             const float* __restrict__ W2, const float* __restrict__ W3) {
    int idx = blockIdx.x * blockDim.x + threadIdx.x;
    if (idx >= 4 * NW * HPAIR) return;
    int mat = idx / (NW * HPAIR);
    int rem = idx - mat * (NW * HPAIR);
    int n = rem / HPAIR;
    int p = rem - n * HPAIR;
    const float* W = (mat == 0) ? W0 : (mat == 1) ? W1 : (mat == 2) ? W2 : W3;
    int gate = n & 3, h = n >> 2;
    int k = p * 2;
    float v0 = 0.f, v1 = 0.f;
    if (h < HDIM) {
        const float* row = W + (size_t)(gate * HDIM + h) * HDIM;
        if (k < HDIM)     v0 = row[k];
        if (k + 1 < HDIM) v1 = row[k + 1];
    }
    uint32_t hi, lo;
    split_pack(v0, v1, hi, lo);
    g_WH[idx] = hi;
    g_WL[idx] = lo;
}

__global__ void prep_z(const float* __restrict__ z) {
    int idx = blockIdx.x * blockDim.x + threadIdx.x;
    if (idx >= PAIRSZ) return;
    int r = idx / HPAIR;
    int p = idx - r * HPAIR;
    int k = p * 2;
    float v0 = (k < HDIM) ? z[(size_t)r * HDIM + k] : 0.f;
    float v1 = (k + 1 < HDIM) ? z[(size_t)r * HDIM + k + 1] : 0.f;
    uint32_t hi, lo;
    split_pack(v0, v1, hi, lo);
    g_zH[idx] = hi;
    g_zL[idx] = lo;
}

// ---------- staging ----------
__device__ __forceinline__ void stage_tile(
    uint32_t* sbuf,
    const uint32_t* __restrict__ aH, const uint32_t* __restrict__ aL,
    const uint32_t* __restrict__ bH, const uint32_t* __restrict__ bL,
    int mBase, int nBase, int p0, int tid)
{
    uint32_t* AsH = sbuf;
    uint32_t* AsL = sbuf + 2560;
    uint32_t* BsH = sbuf + 5120;
    uint32_t* BsL = sbuf + 8320;
#pragma unroll
    for (int i = 0; i < 4; i++) {
        int s = tid + i * NTHREADS;              // 0..1023
        int r = (s >> 2) & (BM - 1);
        int q = s & 3;
        const uint32_t* src = (s < 512) ? aH : aL;
        uint32_t* dst = (s < 512) ? AsH : AsL;
        cp16(dst + r * SMS + q * 4, src + (size_t)(mBase + r) * HPAIR + p0 + q * 4);
    }
#pragma unroll
    for (int i = 0; i < 5; i++) {
        int s = tid + i * NTHREADS;              // 0..1279
        int sp = (s >= 640);
        int ss = sp ? s - 640 : s;
        int r = ss >> 2;
        int q = ss & 3;
        const uint32_t* src = sp ? bL : bH;
        uint32_t* dst = sp ? BsL : BsH;
        cp16(dst + r * SMS + q * 4, src + (size_t)(nBase + r) * HPAIR + p0 + q * 4);
    }
    asm volatile("cp.async.commit_group;");
}

#define MMA1(ACC, AR, BR)                                                        \
    asm volatile("mma.sync.aligned.m16n8k16.row.col.f32.bf16.bf16.f32 "          \
        "{%0,%1,%2,%3}, {%4,%5,%6,%7}, {%8,%9}, {%0,%1,%2,%3};\n"                \
        : "+f"(ACC[0]), "+f"(ACC[1]), "+f"(ACC[2]), "+f"(ACC[3])                 \
        : "r"(AR[0]), "r"(AR[1]), "r"(AR[2]), "r"(AR[3]),                        \
          "r"(BR[0]), "r"(BR[1]));

// Term-major MMA schedule: same-accumulator MMAs are 5 independent MMAs apart,
// hiding HMMA result latency (the R7 tensor=26% stall was the RAW chain of the
// 3 compensation terms hitting the same accumulator back-to-back).
__device__ __forceinline__ void mma_tile(
    const uint32_t* sbuf, float (*acc)[5][4],
    int warpM, int warpN, int gId, int tid4)
{
    const uint32_t* AsH = sbuf;
    const uint32_t* AsL = sbuf + 2560;
    const uint32_t* BsH = sbuf + 5120;
    const uint32_t* BsL = sbuf + 8320;
#pragma unroll
    for (int kk = 0; kk < 2; kk++) {
        const int ko2 = kk * 8;
        uint32_t bH[5][2], bL[5][2];
#pragma unroll
        for (int ni = 0; ni < 5; ni++) {
            int nb = warpN * 40 + ni * 8;
            bH[ni][0] = BsH[(nb + gId) * SMS + ko2 + tid4];
            bH[ni][1] = BsH[(nb + gId) * SMS + ko2 + tid4 + 4];
            bL[ni][0] = BsL[(nb + gId) * SMS + ko2 + tid4];
            bL[ni][1] = BsL[(nb + gId) * SMS + ko2 + tid4 + 4];
        }
#pragma unroll
        for (int mi = 0; mi < 4; mi++) {
            int rb = warpM * 64 + mi * 16;
            uint32_t aH[4], aL[4];
            aH[0] = AsH[(rb + gId) * SMS + ko2 + tid4];
            aH[1] = AsH[(rb + gId + 8) * SMS + ko2 + tid4];
            aH[2] = AsH[(rb + gId) * SMS + ko2 + tid4 + 4];
            aH[3] = AsH[(rb + gId + 8) * SMS + ko2 + tid4 + 4];
            aL[0] = AsL[(rb + gId) * SMS + ko2 + tid4];
            aL[1] = AsL[(rb + gId + 8) * SMS + ko2 + tid4];
            aL[2] = AsL[(rb + gId) * SMS + ko2 + tid4 + 4];
            aL[3] = AsL[(rb + gId + 8) * SMS + ko2 + tid4 + 4];
            // term hl over all ni, then lh, then hh
#pragma unroll
            for (int ni = 0; ni < 5; ni++) { MMA1(acc[mi][ni], aH, bL[ni]); }
#pragma unroll
            for (int ni = 0; ni < 5; ni++) { MMA1(acc[mi][ni], aL, bH[ni]); }
#pragma unroll
            for (int ni = 0; ni < 5; ni++) { MMA1(acc[mi][ni], aH, bH[ni]); }
        }
    }
}

// One fused LSTM cell (bf16x2-compensated GEMMs + gate epilogue).
__device__ void run_cell(
    const uint32_t* __restrict__ xH, const uint32_t* __restrict__ xL,
    const uint32_t* __restrict__ hH, const uint32_t* __restrict__ hL,  // null at t=0
    const float* __restrict__ cprev,                                    // null at t=0
    const uint32_t* __restrict__ WxH, const uint32_t* __restrict__ WxL,
    const uint32_t* __restrict__ WhH, const uint32_t* __restrict__ WhL,
    const float* bias_s,
    uint32_t* __restrict__ hpH, uint32_t* __restrict__ hpL,             // bf16-pair h out
    float* __restrict__ houtF, int hOutStride,                          // optional fp32 h
    float* __restrict__ cout,
    int mBase, int hb)
{
    const int tid   = threadIdx.x;
    const int lane  = tid & 31;
    const int warp  = tid >> 5;
    const int warpM = warp >> 2;
    const int warpN = warp & 3;
    const int gId   = lane >> 2;
    const int tid4  = lane & 3;
    const int nBase = hb * 4;

    float acc[4][5][4];
#pragma unroll
    for (int a = 0; a < 4; a++)
#pragma unroll
        for (int b = 0; b < 5; b++)
#pragma unroll
            for (int c = 0; c < 4; c++) acc[a][b][c] = 0.f;

    const int nT = hH ? 2 * NKT : NKT;

    // prologue: stage tile 0 into buffer 0
    stage_tile(dynsmem, xH, xL, WxH, WxL, mBase, nBase, 0, tid);

#pragma unroll 1
    for (int kt = 0; kt < nT; kt++) {
        asm volatile("cp.async.wait_group 0;");
        __syncthreads();   // tile kt landed; all warps done with tile kt-1
        if (kt + 1 < nT) {
            int k2 = kt + 1;
            const uint32_t *sAH, *sAL, *sBH, *sBL;
            int p0;
            if (k2 < NKT) { sAH = xH; sAL = xL; sBH = WxH; sBL = WxL; p0 = k2 * KPAIR; }
            else          { sAH = hH; sAL = hL; sBH = WhH; sBL = WhL; p0 = (k2 - NKT) * KPAIR; }
            stage_tile(dynsmem + (size_t)(k2 & 1) * BUFU32, sAH, sAL, sBH, sBL,
                       mBase, nBase, p0, tid);
        }
        mma_tile(dynsmem + (size_t)(kt & 1) * BUFU32, acc, warpM, warpN, gId, tid4);
    }

    // epilogue: assemble i,f,g,o per hidden unit via shfl_xor(1)
    __nv_bfloat16* hpH16 = (__nv_bfloat16*)hpH;
    __nv_bfloat16* hpL16 = (__nv_bfloat16*)hpL;
#pragma unroll
    for (int mi = 0; mi < 4; mi++) {
        const int row_r = mBase + warpM * 64 + mi * 16 + gId;
#pragma unroll
        for (int ni = 0; ni < 5; ni++) {
            float c0v = acc[mi][ni][0], c1v = acc[mi][ni][1];
            float c2v = acc[mi][ni][2], c3v = acc[mi][ni][3];
            float p0 = __shfl_xor_sync(0xffffffffu, c0v, 1);
            float p1 = __shfl_xor_sync(0xffffffffu, c1v, 1);
            float p2 = __shfl_xor_sync(0xffffffffu, c2v, 1);
            float p3 = __shfl_xor_sync(0xffffffffu, c3v, 1);

            const int hl = warpN * 10 + ni * 2 + (tid4 >> 1);
            const int h = hb + hl;
            float iraw, fraw, graw, oraw;
            int row;
            if ((tid4 & 1) == 0) {
                iraw = c0v; fraw = c1v; graw = p0; oraw = p1; row = row_r;
            } else {
                iraw = p2; fraw = p3; graw = c2v; oraw = c3v; row = row_r + 8;
            }
            if (h < HDIM) {
                iraw += bias_s[4 * hl + 0];
                fraw += bias_s[4 * hl + 1];
                graw += bias_s[4 * hl + 2];
                oraw += bias_s[4 * hl + 3];
                float ig = 1.f / (1.f + expf(-iraw));
                float fg = 1.f / (1.f + expf(-fraw));
                float gg = tanhf(graw);
                float og = 1.f / (1.f + expf(-oraw));
                float cp = cprev ? cprev[(size_t)row * HDIM + h] : 0.f;
                float cn = fg * cp + ig * gg;
                float hn = og * tanhf(cn);
                cout[(size_t)row * HDIM + h] = cn;
                __nv_bfloat16 hh = __float2bfloat16(hn);
                float rem = hn - __bfloat162float(hh);
                hpH16[(size_t)row * HPAD + h] = hh;
                hpL16[(size_t)row * HPAD + h] = __float2bfloat16(rem);
                if (houtF) houtF[(size_t)row * hOutStride + h] = hn;
            }
        }
    }
}

// ---------- persistent driver kernel ----------
__global__ __launch_bounds__(NTHREADS, 2) void lstm_persistent(
    const float* __restrict__ b_ih0, const float* __restrict__ b_hh0,
    const float* __restrict__ b_ih1, const float* __restrict__ b_hh1,
    float* __restrict__ out, int T)
{
    const int bid   = blockIdx.x;
    const int mBase = (bid >> 3) * BM;   // 32 m-tiles
    const int hb    = (bid & 7) * BH;    // 8 h-blocks
    const int grp   = bid >> 3;          // group = m-tile
    const int tid   = threadIdx.x;

    float* bias0 = (float*)(dynsmem + 2 * BUFU32);
    float* bias1 = bias0 + BNC;
    if (tid < BNC) {
        int gate = tid & 3, hl = tid >> 2, h = hb + hl;
        bias0[tid] = (h < HDIM) ? (b_ih0[gate * HDIM + h] + b_hh0[gate * HDIM + h]) : 0.f;
        bias1[tid] = (h < HDIM) ? (b_ih1[gate * HDIM + h] + b_hh1[gate * HDIM + h]) : 0.f;
    }
    __syncthreads();

    const int WSTEP = NW * HPAIR;

#pragma unroll 1
    for (int t = 0; t < T; t++) {
        const int wr = t & 1, rd = (t + 1) & 1;

        // ---- layer 0 ----
        const uint32_t* x0H = t ? g_oH + (size_t)rd * PAIRSZ : g_zH;
        const uint32_t* x0L = t ? g_oL + (size_t)rd * PAIRSZ : g_zL;
        const uint32_t* hp0H = t ? g_h0H + (size_t)rd * PAIRSZ : nullptr;
        const uint32_t* hp0L = t ? g_h0L + (size_t)rd * PAIRSZ : nullptr;
        run_cell(x0H, x0L, hp0H, hp0L, t ? g_c0 : nullptr,
                 g_WH + 0 * WSTEP, g_WL + 0 * WSTEP,
                 g_WH + 1 * WSTEP, g_WL + 1 * WSTEP,
                 bias0,
                 g_h0H + (size_t)wr * PAIRSZ, g_h0L + (size_t)wr * PAIRSZ,
                 nullptr, 0, g_c0, mBase, hb);
        group_barrier(grp);

        // ---- layer 1 (writes fp32 h into output slice t) ----
        const uint32_t* hp1H = t ? g_oH + (size_t)rd * PAIRSZ : nullptr;
        const uint32_t* hp1L = t ? g_oL + (size_t)rd * PAIRSZ : nullptr;
        run_cell(g_h0H + (size_t)wr * PAIRSZ, g_h0L + (size_t)wr * PAIRSZ,
                 hp1H, hp1L, t ? g_c1 : nullptr,
                 g_WH + 2 * WSTEP, g_WL + 2 * WSTEP,
                 g_WH + 3 * WSTEP, g_WL + 3 * WSTEP,
                 bias1,
                 g_oH + (size_t)wr * PAIRSZ, g_oL + (size_t)wr * PAIRSZ,
                 out + (size_t)t * HDIM, T * HDIM, g_c1, mBase, hb);
        group_barrier(grp);
    }
}

extern "C" void kernel_launch(void* const* d_in, const int* in_sizes, int n_in,
                              void* d_out, int out_size)
{
    const float* z     = (const float*)d_in[0];
    const float* W_ih0 = (const float*)d_in[1];
    const float* W_hh0 = (const float*)d_in[2];
    const float* b_ih0 = (const float*)d_in[3];
    const float* b_hh0 = (const float*)d_in[4];
    const float* W_ih1 = (const float*)d_in[5];
    const float* W_hh1 = (const float*)d_in[6];
    const float* b_ih1 = (const float*)d_in[7];
    const float* b_hh1 = (const float*)d_in[8];
    float* out = (float*)d_out;

    const int Bsz = in_sizes[0] / HDIM;      // 4096
    const int T   = out_size / (Bsz * HDIM); // 64
    const int WSTEP = NW * HPAIR;

    prep_weights<<<(4 * WSTEP + 255) / 256, 256>>>(W_ih0, W_hh0, W_ih1, W_hh1);
    prep_z<<<(PAIRSZ + 255) / 256, 256>>>(z);

    static int attr_done = 0;
    if (!attr_done) {
        cudaFuncSetAttribute(lstm_persistent,
                             cudaFuncAttributeMaxDynamicSharedMemorySize,
                             SMEM_U32 * 4);
        attr_done = 1;
    }
    lstm_persistent<<<NGRP * GRPSZ, NTHREADS, SMEM_U32 * 4>>>(b_ih0, b_hh0, b_ih1, b_hh1,
                                                              out, T);
}

// round 11
// speedup vs baseline: 1.4732x; 1.4732x over previous
#include <cuda_runtime.h>
#include <cuda_bf16.h>
#include <cstdint>

// ---- problem constants ----
#define HDIM 300
#define HPAD 320          // padded k extent (bf16 elems)
#define HPAIR 160         // uint32 (bf16x2) pairs per row
#define BROWS 4096
#define BM 128            // batch rows per CTA
#define BH 40             // hidden units per CTA -> 8 h-blocks
#define BNC 160           // gate-columns per CTA (4*BH)
#define KPAIR 16          // k-pairs per tile (BK=32)
#define SMS 20            // smem row stride in uint32 (16 + 4 pad) -> ldmatrix conflict-free
#define NKT 10            // k-tiles per GEMM segment
#define NTHREADS 256
#define NW 1280           // padded row-permuted weight rows
#define PAIRSZ (BROWS * HPAIR)
#define GRIDSZ 256        // 32 m-tiles x 8 h-blocks = one resident wave
// dynamic smem layout (uint32 units)
#define BUFU32 11520      // AsH(2560)+AsL(2560)+BsH(3200)+BsL(3200)
#define SMEM_U32 (2 * BUFU32 + 2 * BNC)

// ---- device scratch (no allocation allowed) ----
__device__ uint32_t g_zH[PAIRSZ], g_zL[PAIRSZ];
__device__ uint32_t g_h0H[2 * PAIRSZ], g_h0L[2 * PAIRSZ];   // ping-pong layer0 h
__device__ uint32_t g_oH[2 * PAIRSZ], g_oL[2 * PAIRSZ];     // ping-pong layer1 h
__device__ uint32_t g_WH[4 * NW * HPAIR], g_WL[4 * NW * HPAIR]; // Wih0,Whh0,Wih1,Whh1
__device__ float g_c0[BROWS * HDIM], g_c1[BROWS * HDIM];
__device__ unsigned g_bar_count = 0;
__device__ unsigned g_bar_gen = 0;

extern __shared__ uint32_t dynsmem[];

// ---------- helpers ----------
__device__ __forceinline__ uint32_t pack2(__nv_bfloat16 a, __nv_bfloat16 b) {
    return (uint32_t)__bfloat16_as_ushort(a) | ((uint32_t)__bfloat16_as_ushort(b) << 16);
}
__device__ __forceinline__ void split_pack(float v0, float v1, uint32_t& hi, uint32_t& lo) {
    __nv_bfloat16 h0 = __float2bfloat16(v0);
    __nv_bfloat16 h1 = __float2bfloat16(v1);
    float r0 = v0 - __bfloat162float(h0);   // exact
    float r1 = v1 - __bfloat162float(h1);
    hi = pack2(h0, h1);
    lo = pack2(__float2bfloat16(r0), __float2bfloat16(r1));
}
__device__ __forceinline__ void cp16(uint32_t* dst, const uint32_t* src) {
    unsigned sa = (unsigned)__cvta_generic_to_shared(dst);
    asm volatile("cp.async.cg.shared.global [%0], [%1], 16;" :: "r"(sa), "l"(src));
}
__device__ __forceinline__ void ldsm_x4(uint32_t* r, uint32_t saddr) {
    asm volatile("ldmatrix.sync.aligned.m8n8.x4.shared.b16 {%0,%1,%2,%3}, [%4];"
        : "=r"(r[0]), "=r"(r[1]), "=r"(r[2]), "=r"(r[3]) : "r"(saddr));
}
__device__ __forceinline__ void ldsm_x2(uint32_t* r, uint32_t saddr) {
    asm volatile("ldmatrix.sync.aligned.m8n8.x2.shared.b16 {%0,%1}, [%2];"
        : "=r"(r[0]), "=r"(r[1]) : "r"(saddr));
}

// Sense-reversing grid barrier (all 256 CTAs co-resident by construction).
__device__ __forceinline__ void grid_barrier() {
    __threadfence();
    __syncthreads();
    if (threadIdx.x == 0) {
        unsigned gen = *(volatile unsigned*)&g_bar_gen;
        if (atomicAdd(&g_bar_count, 1u) == GRIDSZ - 1u) {
            g_bar_count = 0;
            __threadfence();
            atomicAdd(&g_bar_gen, 1u);
        } else {
            while (*(volatile unsigned*)&g_bar_gen == gen) __nanosleep(32);
        }
        __threadfence();
    }
    __syncthreads();
}

// ---------- prep kernels ----------
__global__ void prep_weights(const float* __restrict__ W0, const float* __restrict__ W1,
                             const float* __restrict__ W2, const float* __restrict__ W3) {
    int idx = blockIdx.x * blockDim.x + threadIdx.x;
    if (idx >= 4 * NW * HPAIR) return;
    int mat = idx / (NW * HPAIR);
    int rem = idx - mat * (NW * HPAIR);
    int n = rem / HPAIR;
    int p = rem - n * HPAIR;
    const float* W = (mat == 0) ? W0 : (mat == 1) ? W1 : (mat == 2) ? W2 : W3;
    int gate = n & 3, h = n >> 2;
    int k = p * 2;
    float v0 = 0.f, v1 = 0.f;
    if (h < HDIM) {
        const float* row = W + (size_t)(gate * HDIM + h) * HDIM;
        if (k < HDIM)     v0 = row[k];
        if (k + 1 < HDIM) v1 = row[k + 1];
    }
    uint32_t hi, lo;
    split_pack(v0, v1, hi, lo);
    g_WH[idx] = hi;
    g_WL[idx] = lo;
}

__global__ void prep_z(const float* __restrict__ z) {
    int idx = blockIdx.x * blockDim.x + threadIdx.x;
    if (idx >= PAIRSZ) return;
    int r = idx / HPAIR;
    int p = idx - r * HPAIR;
    int k = p * 2;
    float v0 = (k < HDIM) ? z[(size_t)r * HDIM + k] : 0.f;
    float v1 = (k + 1 < HDIM) ? z[(size_t)r * HDIM + k + 1] : 0.f;
    uint32_t hi, lo;
    split_pack(v0, v1, hi, lo);
    g_zH[idx] = hi;
    g_zL[idx] = lo;
}

// ---------- staging ----------
__device__ __forceinline__ void stage_tile(
    uint32_t* sbuf,
    const uint32_t* __restrict__ aH, const uint32_t* __restrict__ aL,
    const uint32_t* __restrict__ bH, const uint32_t* __restrict__ bL,
    int mBase, int nBase, int p0, int tid)
{
    uint32_t* AsH = sbuf;
    uint32_t* AsL = sbuf + 2560;
    uint32_t* BsH = sbuf + 5120;
    uint32_t* BsL = sbuf + 8320;
#pragma unroll
    for (int i = 0; i < 4; i++) {
        int s = tid + i * NTHREADS;              // 0..1023
        int r = (s >> 2) & (BM - 1);
        int q = s & 3;
        const uint32_t* src = (s < 512) ? aH : aL;
        uint32_t* dst = (s < 512) ? AsH : AsL;
        cp16(dst + r * SMS + q * 4, src + (size_t)(mBase + r) * HPAIR + p0 + q * 4);
    }
#pragma unroll
    for (int i = 0; i < 5; i++) {
        int s = tid + i * NTHREADS;              // 0..1279
        int sp = (s >= 640);
        int ss = sp ? s - 640 : s;
        int r = ss >> 2;
        int q = ss & 3;
        const uint32_t* src = sp ? bL : bH;
        uint32_t* dst = sp ? BsL : BsH;
        cp16(dst + r * SMS + q * 4, src + (size_t)(nBase + r) * HPAIR + p0 + q * 4);
    }
    asm volatile("cp.async.commit_group;");
}

#define MMA3(ACC, AH, AL, BHI, BLO)                                              \
    asm volatile("mma.sync.aligned.m16n8k16.row.col.f32.bf16.bf16.f32 "          \
        "{%0,%1,%2,%3}, {%4,%5,%6,%7}, {%8,%9}, {%0,%1,%2,%3};\n"                \
        : "+f"(ACC[0]), "+f"(ACC[1]), "+f"(ACC[2]), "+f"(ACC[3])                 \
        : "r"(AH[0]), "r"(AH[1]), "r"(AH[2]), "r"(AH[3]),                        \
          "r"(BLO[0]), "r"(BLO[1]));                                             \
    asm volatile("mma.sync.aligned.m16n8k16.row.col.f32.bf16.bf16.f32 "          \
        "{%0,%1,%2,%3}, {%4,%5,%6,%7}, {%8,%9}, {%0,%1,%2,%3};\n"                \
        : "+f"(ACC[0]), "+f"(ACC[1]), "+f"(ACC[2]), "+f"(ACC[3])                 \
        : "r"(AL[0]), "r"(AL[1]), "r"(AL[2]), "r"(AL[3]),                        \
          "r"(BHI[0]), "r"(BHI[1]));                                             \
    asm volatile("mma.sync.aligned.m16n8k16.row.col.f32.bf16.bf16.f32 "          \
        "{%0,%1,%2,%3}, {%4,%5,%6,%7}, {%8,%9}, {%0,%1,%2,%3};\n"                \
        : "+f"(ACC[0]), "+f"(ACC[1]), "+f"(ACC[2]), "+f"(ACC[3])                 \
        : "r"(AH[0]), "r"(AH[1]), "r"(AH[2]), "r"(AH[3]),                        \
          "r"(BHI[0]), "r"(BHI[1]));

// Fragments via ldmatrix (conflict-free at SMS=20). Same MMA order as the
// 13.8ms baseline; the only change vs that baseline is LDS -> LDSM.
__device__ __forceinline__ void mma_tile(
    uint32_t sbase, float (*acc)[5][4], int warpM, int warpN, int lane)
{
    const uint32_t AsH = sbase;
    const uint32_t AsL = sbase + 2560 * 4;
    const uint32_t BsH = sbase + 5120 * 4;
    const uint32_t BsL = sbase + 8320 * 4;
    const int aRow = lane & 15;
    const int aK4  = (lane & 16) >> 2;          // 0 or 4 (uint32 units)
    const int bRow = (lane & 7) | ((lane & 16) >> 1);
    const int bK4  = (lane & 8) >> 1;           // 0 or 4
    const int bRow2 = lane & 7;                  // for x2 (lanes 0-15 used)
#pragma unroll
    for (int kk = 0; kk < 2; kk++) {
        const int ko2 = kk * 8;
        uint32_t bh[5][2], bl[5][2];
#pragma unroll
        for (int np = 0; np < 2; np++) {         // ni pairs (0,1) and (2,3)
            int nb = warpN * 40 + np * 16;
            uint32_t r4[4];
            ldsm_x4(r4, BsH + (uint32_t)(((nb + bRow) * SMS + ko2 + bK4) << 2));
            bh[2 * np][0] = r4[0]; bh[2 * np][1] = r4[1];
            bh[2 * np + 1][0] = r4[2]; bh[2 * np + 1][1] = r4[3];
            ldsm_x4(r4, BsL + (uint32_t)(((nb + bRow) * SMS + ko2 + bK4) << 2));
            bl[2 * np][0] = r4[0]; bl[2 * np][1] = r4[1];
            bl[2 * np + 1][0] = r4[2]; bl[2 * np + 1][1] = r4[3];
        }
        {
            int nb = warpN * 40 + 32;            // ni = 4
            ldsm_x2(bh[4], BsH + (uint32_t)(((nb + bRow2) * SMS + ko2 + bK4) << 2));
            ldsm_x2(bl[4], BsL + (uint32_t)(((nb + bRow2) * SMS + ko2 + bK4) << 2));
        }
#pragma unroll
        for (int mi = 0; mi < 4; mi++) {
            int rb = warpM * 64 + mi * 16;
            uint32_t aH[4], aL[4];
            ldsm_x4(aH, AsH + (uint32_t)(((rb + aRow) * SMS + ko2 + aK4) << 2));
            ldsm_x4(aL, AsL + (uint32_t)(((rb + aRow) * SMS + ko2 + aK4) << 2));
#pragma unroll
            for (int ni = 0; ni < 5; ni++) {
                MMA3(acc[mi][ni], aH, aL, bh[ni], bl[ni]);
            }
        }
    }
}

// One fused LSTM cell (bf16x2-compensated GEMMs + gate epilogue).
__device__ void run_cell(
    uint32_t smbase,
    const uint32_t* __restrict__ xH, const uint32_t* __restrict__ xL,
    const uint32_t* __restrict__ hH, const uint32_t* __restrict__ hL,  // null at t=0
    const float* __restrict__ cprev,                                    // null at t=0
    const uint32_t* __restrict__ WxH, const uint32_t* __restrict__ WxL,
    const uint32_t* __restrict__ WhH, const uint32_t* __restrict__ WhL,
    const float* bias_s,
    uint32_t* __restrict__ hpH, uint32_t* __restrict__ hpL,             // bf16-pair h out
    float* __restrict__ houtF, int hOutStride,                          // optional fp32 h
    float* __restrict__ cout,
    int mBase, int hb)
{
    const int tid   = threadIdx.x;
    const int lane  = tid & 31;
    const int warp  = tid >> 5;
    const int warpM = warp >> 2;
    const int warpN = warp & 3;
    const int gId   = lane >> 2;
    const int tid4  = lane & 3;
    const int nBase = hb * 4;

    float acc[4][5][4];
#pragma unroll
    for (int a = 0; a < 4; a++)
#pragma unroll
        for (int b = 0; b < 5; b++)
#pragma unroll
            for (int c = 0; c < 4; c++) acc[a][b][c] = 0.f;

    const int nT = hH ? 2 * NKT : NKT;

    // prologue: stage tile 0 into buffer 0
    stage_tile(dynsmem, xH, xL, WxH, WxL, mBase, nBase, 0, tid);

#pragma unroll 1
    for (int kt = 0; kt < nT; kt++) {
        asm volatile("cp.async.wait_group 0;");
        __syncthreads();   // tile kt landed; all warps done with tile kt-1
        if (kt + 1 < nT) {
            int k2 = kt + 1;
            const uint32_t *sAH, *sAL, *sBH, *sBL;
            int p0;
            if (k2 < NKT) { sAH = xH; sAL = xL; sBH = WxH; sBL = WxL; p0 = k2 * KPAIR; }
            else          { sAH = hH; sAL = hL; sBH = WhH; sBL = WhL; p0 = (k2 - NKT) * KPAIR; }
            stage_tile(dynsmem + (size_t)(k2 & 1) * BUFU32, sAH, sAL, sBH, sBL,
                       mBase, nBase, p0, tid);
        }
        mma_tile(smbase + (uint32_t)((kt & 1) * BUFU32 * 4), acc, warpM, warpN, lane);
    }

    // epilogue: assemble i,f,g,o per hidden unit via shfl_xor(1)
    __nv_bfloat16* hpH16 = (__nv_bfloat16*)hpH;
    __nv_bfloat16* hpL16 = (__nv_bfloat16*)hpL;
#pragma unroll
    for (int mi = 0; mi < 4; mi++) {
        const int row_r = mBase + warpM * 64 + mi * 16 + gId;
#pragma unroll
        for (int ni = 0; ni < 5; ni++) {
            float c0v = acc[mi][ni][0], c1v = acc[mi][ni][1];
            float c2v = acc[mi][ni][2], c3v = acc[mi][ni][3];
            float p0 = __shfl_xor_sync(0xffffffffu, c0v, 1);
            float p1 = __shfl_xor_sync(0xffffffffu, c1v, 1);
            float p2 = __shfl_xor_sync(0xffffffffu, c2v, 1);
            float p3 = __shfl_xor_sync(0xffffffffu, c3v, 1);

            const int hl = warpN * 10 + ni * 2 + (tid4 >> 1);
            const int h = hb + hl;
            float iraw, fraw, graw, oraw;
            int row;
            if ((tid4 & 1) == 0) {
                iraw = c0v; fraw = c1v; graw = p0; oraw = p1; row = row_r;
            } else {
                iraw = p2; fraw = p3; graw = c2v; oraw = c3v; row = row_r + 8;
            }
            if (h < HDIM) {
                iraw += bias_s[4 * hl + 0];
                fraw += bias_s[4 * hl + 1];
                graw += bias_s[4 * hl + 2];
                oraw += bias_s[4 * hl + 3];
                float ig = 1.f / (1.f + expf(-iraw));
                float fg = 1.f / (1.f + expf(-fraw));
                float gg = tanhf(graw);
                float og = 1.f / (1.f + expf(-oraw));
                float cp = cprev ? cprev[(size_t)row * HDIM + h] : 0.f;
                float cn = fg * cp + ig * gg;
                float hn = og * tanhf(cn);
                cout[(size_t)row * HDIM + h] = cn;
                __nv_bfloat16 hh = __float2bfloat16(hn);
                float rem = hn - __bfloat162float(hh);
                hpH16[(size_t)row * HPAD + h] = hh;
                hpL16[(size_t)row * HPAD + h] = __float2bfloat16(rem);
                if (houtF) houtF[(size_t)row * hOutStride + h] = hn;
            }
        }
    }
}

// ---------- persistent driver kernel ----------
__global__ __launch_bounds__(NTHREADS, 2) void lstm_persistent(
    const float* __restrict__ b_ih0, const float* __restrict__ b_hh0,
    const float* __restrict__ b_ih1, const float* __restrict__ b_hh1,
    float* __restrict__ out, int T)
{
    const int bid   = blockIdx.x;
    const int mBase = (bid >> 3) * BM;   // 32 m-tiles
    const int hb    = (bid & 7) * BH;    // 8 h-blocks
    const int tid   = threadIdx.x;

    const uint32_t smbase = (uint32_t)__cvta_generic_to_shared(dynsmem);

    float* bias0 = (float*)(dynsmem + 2 * BUFU32);
    float* bias1 = bias0 + BNC;
    if (tid < BNC) {
        int gate = tid & 3, hl = tid >> 2, h = hb + hl;
        bias0[tid] = (h < HDIM) ? (b_ih0[gate * HDIM + h] + b_hh0[gate * HDIM + h]) : 0.f;
        bias1[tid] = (h < HDIM) ? (b_ih1[gate * HDIM + h] + b_hh1[gate * HDIM + h]) : 0.f;
    }
    __syncthreads();

    const int WSTEP = NW * HPAIR;

#pragma unroll 1
    for (int t = 0; t < T; t++) {
        const int wr = t & 1, rd = (t + 1) & 1;

        // ---- layer 0 ----
        const uint32_t* x0H = t ? g_oH + (size_t)rd * PAIRSZ : g_zH;
        const uint32_t* x0L = t ? g_oL + (size_t)rd * PAIRSZ : g_zL;
        const uint32_t* hp0H = t ? g_h0H + (size_t)rd * PAIRSZ : nullptr;
        const uint32_t* hp0L = t ? g_h0L + (size_t)rd * PAIRSZ : nullptr;
        run_cell(smbase, x0H, x0L, hp0H, hp0L, t ? g_c0 : nullptr,
                 g_WH + 0 * WSTEP, g_WL + 0 * WSTEP,
                 g_WH + 1 * WSTEP, g_WL + 1 * WSTEP,
                 bias0,
                 g_h0H + (size_t)wr * PAIRSZ, g_h0L + (size_t)wr * PAIRSZ,
                 nullptr, 0, g_c0, mBase, hb);
        grid_barrier();

        // ---- layer 1 (writes fp32 h into output slice t) ----
        const uint32_t* hp1H = t ? g_oH + (size_t)rd * PAIRSZ : nullptr;
        const uint32_t* hp1L = t ? g_oL + (size_t)rd * PAIRSZ : nullptr;
        run_cell(smbase, g_h0H + (size_t)wr * PAIRSZ, g_h0L + (size_t)wr * PAIRSZ,
                 hp1H, hp1L, t ? g_c1 : nullptr,
                 g_WH + 2 * WSTEP, g_WL + 2 * WSTEP,
                 g_WH + 3 * WSTEP, g_WL + 3 * WSTEP,
                 bias1,
                 g_oH + (size_t)wr * PAIRSZ, g_oL + (size_t)wr * PAIRSZ,
                 out + (size_t)t * HDIM, T * HDIM, g_c1, mBase, hb);
        grid_barrier();
    }
}

extern "C" void kernel_launch(void* const* d_in, const int* in_sizes, int n_in,
                              void* d_out, int out_size)
{
    const float* z     = (const float*)d_in[0];
    const float* W_ih0 = (const float*)d_in[1];
    const float* W_hh0 = (const float*)d_in[2];
    const float* b_ih0 = (const float*)d_in[3];
    const float* b_hh0 = (const float*)d_in[4];
    const float* W_ih1 = (const float*)d_in[5];
    const float* W_hh1 = (const float*)d_in[6];
    const float* b_ih1 = (const float*)d_in[7];
    const float* b_hh1 = (const float*)d_in[8];
    float* out = (float*)d_out;

    const int Bsz = in_sizes[0] / HDIM;      // 4096
    const int T   = out_size / (Bsz * HDIM); // 64
    const int WSTEP = NW * HPAIR;

    prep_weights<<<(4 * WSTEP + 255) / 256, 256>>>(W_ih0, W_hh0, W_ih1, W_hh1);
    prep_z<<<(PAIRSZ + 255) / 256, 256>>>(z);

    static int attr_done = 0;
    if (!attr_done) {
        cudaFuncSetAttribute(lstm_persistent,
                             cudaFuncAttributeMaxDynamicSharedMemorySize,
                             SMEM_U32 * 4);
        attr_done = 1;
    }
    lstm_persistent<<<GRIDSZ, NTHREADS, SMEM_U32 * 4>>>(b_ih0, b_hh0, b_ih1, b_hh1,
                                                        out, T);
}

// round 12
// speedup vs baseline: 1.5726x; 1.0675x over previous
#include <cuda_runtime.h>
#include <cuda_bf16.h>
#include <cstdint>

// ---- problem constants ----
#define HDIM 300
#define HPAD 320          // padded k extent (bf16 elems)
#define HPAIR 160         // uint32 (bf16x2) pairs per row
#define BROWS 4096
#define BM 128            // batch rows per CTA
#define BH 40             // hidden units per CTA -> 8 h-blocks
#define BNC 160           // gate-columns per CTA (4*BH)
#define KPAIR 16          // k-pairs per tile (BK=32)
#define SMS 20            // smem row stride in uint32 (16 + 4 pad) -> ldmatrix conflict-free
#define NKT 10            // k-tiles per GEMM segment
#define NTHREADS 256
#define NW 1280           // padded row-permuted weight rows
#define PAIRSZ (BROWS * HPAIR)
#define NGRP 32           // one independent sync group per m-tile
#define GRPSZ 8           // 8 h-block CTAs per group
// dynamic smem layout (uint32 units)
#define BUFU32 11520      // AsH(2560)+AsL(2560)+BsH(3200)+BsL(3200)
#define SMEM_U32 (2 * BUFU32 + 2 * BNC)

// ---- device scratch (no allocation allowed) ----
__device__ uint32_t g_zH[PAIRSZ], g_zL[PAIRSZ];
__device__ uint32_t g_h0H[2 * PAIRSZ], g_h0L[2 * PAIRSZ];   // ping-pong layer0 h
__device__ uint32_t g_oH[2 * PAIRSZ], g_oL[2 * PAIRSZ];     // ping-pong layer1 h
__device__ uint32_t g_WH[4 * NW * HPAIR], g_WL[4 * NW * HPAIR]; // Wih0,Whh0,Wih1,Whh1
__device__ float g_c0[BROWS * HDIM], g_c1[BROWS * HDIM];
__device__ unsigned g_gc[NGRP * 32];   // per-group arrival counters (line-padded)
__device__ unsigned g_gg[NGRP * 32];   // per-group generations

extern __shared__ uint32_t dynsmem[];

// ---------- helpers ----------
__device__ __forceinline__ uint32_t pack2(__nv_bfloat16 a, __nv_bfloat16 b) {
    return (uint32_t)__bfloat16_as_ushort(a) | ((uint32_t)__bfloat16_as_ushort(b) << 16);
}
__device__ __forceinline__ void split_pack(float v0, float v1, uint32_t& hi, uint32_t& lo) {
    __nv_bfloat16 h0 = __float2bfloat16(v0);
    __nv_bfloat16 h1 = __float2bfloat16(v1);
    float r0 = v0 - __bfloat162float(h0);   // exact
    float r1 = v1 - __bfloat162float(h1);
    hi = pack2(h0, h1);
    lo = pack2(__float2bfloat16(r0), __float2bfloat16(r1));
}
__device__ __forceinline__ void cp16(uint32_t* dst, const uint32_t* src) {
    unsigned sa = (unsigned)__cvta_generic_to_shared(dst);
    asm volatile("cp.async.cg.shared.global [%0], [%1], 16;" :: "r"(sa), "l"(src));
}
__device__ __forceinline__ void ldsm_x4(uint32_t* r, uint32_t saddr) {
    asm volatile("ldmatrix.sync.aligned.m8n8.x4.shared.b16 {%0,%1,%2,%3}, [%4];"
        : "=r"(r[0]), "=r"(r[1]), "=r"(r[2]), "=r"(r[3]) : "r"(saddr));
}
__device__ __forceinline__ void ldsm_x2(uint32_t* r, uint32_t saddr) {
    asm volatile("ldmatrix.sync.aligned.m8n8.x2.shared.b16 {%0,%1}, [%2];"
        : "=r"(r[0]), "=r"(r[1]) : "r"(saddr));
}
__device__ __forceinline__ unsigned atom_add_acqrel(unsigned* p, unsigned v) {
    unsigned old;
    asm volatile("atom.add.acq_rel.gpu.u32 %0, [%1], %2;"
        : "=r"(old) : "l"(p), "r"(v) : "memory");
    return old;
}
__device__ __forceinline__ unsigned ld_acquire(const unsigned* p) {
    unsigned v;
    asm volatile("ld.acquire.gpu.u32 %0, [%1];" : "=r"(v) : "l"(p) : "memory");
    return v;
}

// Barrier over the 8 CTAs of one m-tile group. All cross-CTA dataflow
// (h0/o pairs, c state) is group-local, so the 32 groups free-run and
// per-step skew is absorbed instead of serialized chip-wide.
// acq_rel arrival orders each CTA's prior global writes; acquire polling
// pairs with the leader's release — no standalone membar needed.
__device__ __forceinline__ void group_barrier(int grp) {
    __syncthreads();
    if (threadIdx.x == 0) {
        unsigned* cnt = &g_gc[grp * 32];
        unsigned* gen = &g_gg[grp * 32];
        unsigned g = ld_acquire(gen);
        unsigned old = atom_add_acqrel(cnt, 1u);
        if (old == GRPSZ - 1u) {
            atom_add_acqrel(cnt, (unsigned)(-GRPSZ));   // reset before gen bump
            atom_add_acqrel(gen, 1u);
        } else {
            while (ld_acquire(gen) == g) __nanosleep(32);
        }
    }
    __syncthreads();
}

// ---------- prep kernels ----------
__global__ void prep_weights(const float* __restrict__ W0, const float* __restrict__ W1,
                             const float* __restrict__ W2, const float* __restrict__ W3) {
    int idx = blockIdx.x * blockDim.x + threadIdx.x;
    if (idx >= 4 * NW * HPAIR) return;
    int mat = idx / (NW * HPAIR);
    int rem = idx - mat * (NW * HPAIR);
    int n = rem / HPAIR;
    int p = rem - n * HPAIR;
    const float* W = (mat == 0) ? W0 : (mat == 1) ? W1 : (mat == 2) ? W2 : W3;
    int gate = n & 3, h = n >> 2;
    int k = p * 2;
    float v0 = 0.f, v1 = 0.f;
    if (h < HDIM) {
        const float* row = W + (size_t)(gate * HDIM + h) * HDIM;
        if (k < HDIM)     v0 = row[k];
        if (k + 1 < HDIM) v1 = row[k + 1];
    }
    uint32_t hi, lo;
    split_pack(v0, v1, hi, lo);
    g_WH[idx] = hi;
    g_WL[idx] = lo;
}

__global__ void prep_z(const float* __restrict__ z) {
    int idx = blockIdx.x * blockDim.x + threadIdx.x;
    if (idx >= PAIRSZ) return;
    int r = idx / HPAIR;
    int p = idx - r * HPAIR;
    int k = p * 2;
    float v0 = (k < HDIM) ? z[(size_t)r * HDIM + k] : 0.f;
    float v1 = (k + 1 < HDIM) ? z[(size_t)r * HDIM + k + 1] : 0.f;
    uint32_t hi, lo;
    split_pack(v0, v1, hi, lo);
    g_zH[idx] = hi;
    g_zL[idx] = lo;
}

// ---------- staging (A and B halves split so B can be prefetched) ----------
__device__ __forceinline__ void stage_A(
    uint32_t* sbuf,
    const uint32_t* __restrict__ aH, const uint32_t* __restrict__ aL,
    int mBase, int p0, int tid)
{
    uint32_t* AsH = sbuf;
    uint32_t* AsL = sbuf + 2560;
#pragma unroll
    for (int i = 0; i < 4; i++) {
        int s = tid + i * NTHREADS;              // 0..1023
        int r = (s >> 2) & (BM - 1);
        int q = s & 3;
        const uint32_t* src = (s < 512) ? aH : aL;
        uint32_t* dst = (s < 512) ? AsH : AsL;
        cp16(dst + r * SMS + q * 4, src + (size_t)(mBase + r) * HPAIR + p0 + q * 4);
    }
}
__device__ __forceinline__ void stage_B(
    uint32_t* sbuf,
    const uint32_t* __restrict__ bH, const uint32_t* __restrict__ bL,
    int nBase, int p0, int tid)
{
    uint32_t* BsH = sbuf + 5120;
    uint32_t* BsL = sbuf + 8320;
#pragma unroll
    for (int i = 0; i < 5; i++) {
        int s = tid + i * NTHREADS;              // 0..1279
        int sp = (s >= 640);
        int ss = sp ? s - 640 : s;
        int r = ss >> 2;
        int q = ss & 3;
        const uint32_t* src = sp ? bL : bH;
        uint32_t* dst = sp ? BsL : BsH;
        cp16(dst + r * SMS + q * 4, src + (size_t)(nBase + r) * HPAIR + p0 + q * 4);
    }
}

#define MMA3(ACC, AH, AL, BHI, BLO)                                              \
    asm volatile("mma.sync.aligned.m16n8k16.row.col.f32.bf16.bf16.f32 "          \
        "{%0,%1,%2,%3}, {%4,%5,%6,%7}, {%8,%9}, {%0,%1,%2,%3};\n"                \
        : "+f"(ACC[0]), "+f"(ACC[1]), "+f"(ACC[2]), "+f"(ACC[3])                 \
        : "r"(AH[0]), "r"(AH[1]), "r"(AH[2]), "r"(AH[3]),                        \
          "r"(BLO[0]), "r"(BLO[1]));                                             \
    asm volatile("mma.sync.aligned.m16n8k16.row.col.f32.bf16.bf16.f32 "          \
        "{%0,%1,%2,%3}, {%4,%5,%6,%7}, {%8,%9}, {%0,%1,%2,%3};\n"                \
        : "+f"(ACC[0]), "+f"(ACC[1]), "+f"(ACC[2]), "+f"(ACC[3])                 \
        : "r"(AL[0]), "r"(AL[1]), "r"(AL[2]), "r"(AL[3]),                        \
          "r"(BHI[0]), "r"(BHI[1]));                                             \
    asm volatile("mma.sync.aligned.m16n8k16.row.col.f32.bf16.bf16.f32 "          \
        "{%0,%1,%2,%3}, {%4,%5,%6,%7}, {%8,%9}, {%0,%1,%2,%3};\n"                \
        : "+f"(ACC[0]), "+f"(ACC[1]), "+f"(ACC[2]), "+f"(ACC[3])                 \
        : "r"(AH[0]), "r"(AH[1]), "r"(AH[2]), "r"(AH[3]),                        \
          "r"(BHI[0]), "r"(BHI[1]));

// Fragments via ldmatrix (conflict-free at SMS=20). Identical MMA order to
// the passing R11 kernel.
__device__ __forceinline__ void mma_tile(
    uint32_t sbase, float (*acc)[5][4], int warpM, int warpN, int lane)
{
    const uint32_t AsH = sbase;
    const uint32_t AsL = sbase + 2560 * 4;
    const uint32_t BsH = sbase + 5120 * 4;
    const uint32_t BsL = sbase + 8320 * 4;
    const int aRow = lane & 15;
    const int aK4  = (lane & 16) >> 2;          // 0 or 4 (uint32 units)
    const int bRow = (lane & 7) | ((lane & 16) >> 1);
    const int bK4  = (lane & 8) >> 1;           // 0 or 4
    const int bRow2 = lane & 7;                  // for x2 (lanes 0-15 used)
#pragma unroll
    for (int kk = 0; kk < 2; kk++) {
        const int ko2 = kk * 8;
        uint32_t bh[5][2], bl[5][2];
#pragma unroll
        for (int np = 0; np < 2; np++) {         // ni pairs (0,1) and (2,3)
            int nb = warpN * 40 + np * 16;
            uint32_t r4[4];
            ldsm_x4(r4, BsH + (uint32_t)(((nb + bRow) * SMS + ko2 + bK4) << 2));
            bh[2 * np][0] = r4[0]; bh[2 * np][1] = r4[1];
            bh[2 * np + 1][0] = r4[2]; bh[2 * np + 1][1] = r4[3];
            ldsm_x4(r4, BsL + (uint32_t)(((nb + bRow) * SMS + ko2 + bK4) << 2));
            bl[2 * np][0] = r4[0]; bl[2 * np][1] = r4[1];
            bl[2 * np + 1][0] = r4[2]; bl[2 * np + 1][1] = r4[3];
        }
        {
            int nb = warpN * 40 + 32;            // ni = 4
            ldsm_x2(bh[4], BsH + (uint32_t)(((nb + bRow2) * SMS + ko2 + bK4) << 2));
            ldsm_x2(bl[4], BsL + (uint32_t)(((nb + bRow2) * SMS + ko2 + bK4) << 2));
        }
#pragma unroll
        for (int mi = 0; mi < 4; mi++) {
            int rb = warpM * 64 + mi * 16;
            uint32_t aH[4], aL[4];
            ldsm_x4(aH, AsH + (uint32_t)(((rb + aRow) * SMS + ko2 + aK4) << 2));
            ldsm_x4(aL, AsL + (uint32_t)(((rb + aRow) * SMS + ko2 + aK4) << 2));
#pragma unroll
            for (int ni = 0; ni < 5; ni++) {
                MMA3(acc[mi][ni], aH, aL, bh[ni], bl[ni]);
            }
        }
    }
}

// One fused LSTM cell (bf16x2-compensated GEMMs + gate epilogue).
// b0pre: B half of tile 0 was already prefetched (pre-barrier) into buffer 0.
__device__ void run_cell(
    uint32_t smbase,
    const uint32_t* __restrict__ xH, const uint32_t* __restrict__ xL,
    const uint32_t* __restrict__ hH, const uint32_t* __restrict__ hL,  // null at t=0
    const float* __restrict__ cprev,                                    // null at t=0
    const uint32_t* __restrict__ WxH, const uint32_t* __restrict__ WxL,
    const uint32_t* __restrict__ WhH, const uint32_t* __restrict__ WhL,
    const float* bias_s,
    uint32_t* __restrict__ hpH, uint32_t* __restrict__ hpL,             // bf16-pair h out
    float* __restrict__ houtF, int hOutStride,                          // optional fp32 h
    float* __restrict__ cout,
    int mBase, int hb, int b0pre)
{
    const int tid   = threadIdx.x;
    const int lane  = tid & 31;
    const int warp  = tid >> 5;
    const int warpM = warp >> 2;
    const int warpN = warp & 3;
    const int gId   = lane >> 2;
    const int tid4  = lane & 3;
    const int nBase = hb * 4;

    float acc[4][5][4];
#pragma unroll
    for (int a = 0; a < 4; a++)
#pragma unroll
        for (int b = 0; b < 5; b++)
#pragma unroll
            for (int c = 0; c < 4; c++) acc[a][b][c] = 0.f;

    const int nT = hH ? 2 * NKT : NKT;

    // prologue: stage tile 0 into buffer 0 (B may be pre-staged)
    stage_A(dynsmem, xH, xL, mBase, 0, tid);
    if (!b0pre) stage_B(dynsmem, WxH, WxL, nBase, 0, tid);
    asm volatile("cp.async.commit_group;");

#pragma unroll 1
    for (int kt = 0; kt < nT; kt++) {
        asm volatile("cp.async.wait_group 0;");
        __syncthreads();   // tile kt landed; all warps done with tile kt-1
        if (kt + 1 < nT) {
            int k2 = kt + 1;
            const uint32_t *sAH, *sAL, *sBH, *sBL;
            int p0;
            if (k2 < NKT) { sAH = xH; sAL = xL; sBH = WxH; sBL = WxL; p0 = k2 * KPAIR; }
            else          { sAH = hH; sAL = hL; sBH = WhH; sBL = WhL; p0 = (k2 - NKT) * KPAIR; }
            uint32_t* buf = dynsmem + (size_t)(k2 & 1) * BUFU32;
            stage_A(buf, sAH, sAL, mBase, p0, tid);
            stage_B(buf, sBH, sBL, nBase, p0, tid);
            asm volatile("cp.async.commit_group;");
        }
        mma_tile(smbase + (uint32_t)((kt & 1) * BUFU32 * 4), acc, warpM, warpN, lane);
    }

    // epilogue: assemble i,f,g,o per hidden unit via shfl_xor(1)
    __nv_bfloat16* hpH16 = (__nv_bfloat16*)hpH;
    __nv_bfloat16* hpL16 = (__nv_bfloat16*)hpL;
#pragma unroll
    for (int mi = 0; mi < 4; mi++) {
        const int row_r = mBase + warpM * 64 + mi * 16 + gId;
#pragma unroll
        for (int ni = 0; ni < 5; ni++) {
            float c0v = acc[mi][ni][0], c1v = acc[mi][ni][1];
            float c2v = acc[mi][ni][2], c3v = acc[mi][ni][3];
            float p0 = __shfl_xor_sync(0xffffffffu, c0v, 1);
            float p1 = __shfl_xor_sync(0xffffffffu, c1v, 1);
            float p2 = __shfl_xor_sync(0xffffffffu, c2v, 1);
            float p3 = __shfl_xor_sync(0xffffffffu, c3v, 1);

            const int hl = warpN * 10 + ni * 2 + (tid4 >> 1);
            const int h = hb + hl;
            float iraw, fraw, graw, oraw;
            int row;
            if ((tid4 & 1) == 0) {
                iraw = c0v; fraw = c1v; graw = p0; oraw = p1; row = row_r;
            } else {
                iraw = p2; fraw = p3; graw = c2v; oraw = c3v; row = row_r + 8;
            }
            if (h < HDIM) {
                iraw += bias_s[4 * hl + 0];
                fraw += bias_s[4 * hl + 1];
                graw += bias_s[4 * hl + 2];
                oraw += bias_s[4 * hl + 3];
                float ig = 1.f / (1.f + expf(-iraw));
                float fg = 1.f / (1.f + expf(-fraw));
                float gg = tanhf(graw);
                float og = 1.f / (1.f + expf(-oraw));
                float cp = cprev ? cprev[(size_t)row * HDIM + h] : 0.f;
                float cn = fg * cp + ig * gg;
                float hn = og * tanhf(cn);
                cout[(size_t)row * HDIM + h] = cn;
                __nv_bfloat16 hh = __float2bfloat16(hn);
                float rem = hn - __bfloat162float(hh);
                hpH16[(size_t)row * HPAD + h] = hh;
                hpL16[(size_t)row * HPAD + h] = __float2bfloat16(rem);
                if (houtF) houtF[(size_t)row * hOutStride + h] = hn;
            }
        }
    }
}

// ---------- persistent driver kernel ----------
__global__ __launch_bounds__(NTHREADS, 2) void lstm_persistent(
    const float* __restrict__ b_ih0, const float* __restrict__ b_hh0,
    const float* __restrict__ b_ih1, const float* __restrict__ b_hh1,
    float* __restrict__ out, int T)
{
    const int bid   = blockIdx.x;
    const int mBase = (bid >> 3) * BM;   // 32 m-tiles
    const int hb    = (bid & 7) * BH;    // 8 h-blocks
    const int grp   = bid >> 3;          // sync group = m-tile
    const int tid   = threadIdx.x;
    const int nBase = hb * 4;

    const uint32_t smbase = (uint32_t)__cvta_generic_to_shared(dynsmem);

    float* bias0 = (float*)(dynsmem + 2 * BUFU32);
    float* bias1 = bias0 + BNC;
    if (tid < BNC) {
        int gate = tid & 3, hl = tid >> 2, h = hb + hl;
        bias0[tid] = (h < HDIM) ? (b_ih0[gate * HDIM + h] + b_hh0[gate * HDIM + h]) : 0.f;
        bias1[tid] = (h < HDIM) ? (b_ih1[gate * HDIM + h] + b_hh1[gate * HDIM + h]) : 0.f;
    }
    __syncthreads();

    const int WSTEP = NW * HPAIR;

    // prefetch B tile0 for the first cell (layer0: Wih0)
    stage_B(dynsmem, g_WH + 0 * WSTEP, g_WL + 0 * WSTEP, nBase, 0, tid);
    asm volatile("cp.async.commit_group;");

#pragma unroll 1
    for (int t = 0; t < T; t++) {
        const int wr = t & 1, rd = (t + 1) & 1;

        // ---- layer 0 ----
        const uint32_t* x0H = t ? g_oH + (size_t)rd * PAIRSZ : g_zH;
        const uint32_t* x0L = t ? g_oL + (size_t)rd * PAIRSZ : g_zL;
        const uint32_t* hp0H = t ? g_h0H + (size_t)rd * PAIRSZ : nullptr;
        const uint32_t* hp0L = t ? g_h0L + (size_t)rd * PAIRSZ : nullptr;
        run_cell(smbase, x0H, x0L, hp0H, hp0L, t ? g_c0 : nullptr,
                 g_WH + 0 * WSTEP, g_WL + 0 * WSTEP,
                 g_WH + 1 * WSTEP, g_WL + 1 * WSTEP,
                 bias0,
                 g_h0H + (size_t)wr * PAIRSZ, g_h0L + (size_t)wr * PAIRSZ,
                 nullptr, 0, g_c0, mBase, hb, 1);

        // prefetch B tile0 for layer1 (Wih1) before waiting on the group
        stage_B(dynsmem, g_WH + 2 * WSTEP, g_WL + 2 * WSTEP, nBase, 0, tid);
        asm volatile("cp.async.commit_group;");
        group_barrier(grp);

        // ---- layer 1 (writes fp32 h into output slice t) ----
        const uint32_t* hp1H = t ? g_oH + (size_t)rd * PAIRSZ : nullptr;
        const uint32_t* hp1L = t ? g_oL + (size_t)rd * PAIRSZ : nullptr;
        run_cell(smbase, g_h0H + (size_t)wr * PAIRSZ, g_h0L + (size_t)wr * PAIRSZ,
                 hp1H, hp1L, t ? g_c1 : nullptr,
                 g_WH + 2 * WSTEP, g_WL + 2 * WSTEP,
                 g_WH + 3 * WSTEP, g_WL + 3 * WSTEP,
                 bias1,
                 g_oH + (size_t)wr * PAIRSZ, g_oL + (size_t)wr * PAIRSZ,
                 out + (size_t)t * HDIM, T * HDIM, g_c1, mBase, hb, 1);

        if (t + 1 < T) {   // prefetch B tile0 for next layer0 (Wih0)
            stage_B(dynsmem, g_WH + 0 * WSTEP, g_WL + 0 * WSTEP, nBase, 0, tid);
            asm volatile("cp.async.commit_group;");
        }
        group_barrier(grp);
    }
}

extern "C" void kernel_launch(void* const* d_in, const int* in_sizes, int n_in,
                              void* d_out, int out_size)
{
    const float* z     = (const float*)d_in[0];
    const float* W_ih0 = (const float*)d_in[1];
    const float* W_hh0 = (const float*)d_in[2];
    const float* b_ih0 = (const float*)d_in[3];
    const float* b_hh0 = (const float*)d_in[4];
    const float* W_ih1 = (const float*)d_in[5];
    const float* W_hh1 = (const float*)d_in[6];
    const float* b_ih1 = (const float*)d_in[7];
    const float* b_hh1 = (const float*)d_in[8];
    float* out = (float*)d_out;

    const int Bsz = in_sizes[0] / HDIM;      // 4096
    const int T   = out_size / (Bsz * HDIM); // 64
    const int WSTEP = NW * HPAIR;

    prep_weights<<<(4 * WSTEP + 255) / 256, 256>>>(W_ih0, W_hh0, W_ih1, W_hh1);
    prep_z<<<(PAIRSZ + 255) / 256, 256>>>(z);

    static int attr_done = 0;
    if (!attr_done) {
        cudaFuncSetAttribute(lstm_persistent,
                             cudaFuncAttributeMaxDynamicSharedMemorySize,
                             SMEM_U32 * 4);
        attr_done = 1;
    }
    lstm_persistent<<<NGRP * GRPSZ, NTHREADS, SMEM_U32 * 4>>>(b_ih0, b_hh0, b_ih1, b_hh1,
                                                              out, T);
}

// round 13
// speedup vs baseline: 1.7389x; 1.1057x over previous
#include <cuda_runtime.h>
#include <cuda_bf16.h>
#include <cstdint>

// ---- problem constants ----
#define HDIM 300
#define HPAD 320          // padded k extent (bf16 elems)
#define HPAIR 160         // uint32 (bf16x2) pairs per row
#define BROWS 4096
#define BM 128            // batch rows per CTA
#define BH 40             // hidden units per CTA -> 8 h-blocks
#define BNC 160           // gate-columns per CTA (4*BH)
#define KPAIR 16          // k-pairs per tile (BK=32)
#define SMS 20            // smem row stride in uint32 (16 + 4 pad) -> ldmatrix conflict-free
#define NKT 10            // k-tiles per GEMM segment
#define NTHREADS 256
#define NW 1280           // padded row-permuted weight rows
#define PAIRSZ (BROWS * HPAIR)
#define NGRP 32           // one independent sync group per m-tile
#define GRPSZ 8           // 8 h-block CTAs per group
// dynamic smem layout (uint32 units)
#define BUFU32 11520      // AsH(2560)+AsL(2560)+BsH(3200)+BsL(3200)
#define SMEM_U32 (2 * BUFU32 + 2 * BNC)

// ---- device scratch (no allocation allowed) ----
__device__ uint32_t g_zH[PAIRSZ], g_zL[PAIRSZ];
__device__ uint32_t g_h0H[2 * PAIRSZ], g_h0L[2 * PAIRSZ];   // ping-pong layer0 h
__device__ uint32_t g_oH[2 * PAIRSZ], g_oL[2 * PAIRSZ];     // ping-pong layer1 h
__device__ uint32_t g_WH[4 * NW * HPAIR], g_WL[4 * NW * HPAIR]; // Wih0,Whh0,Wih1,Whh1
__device__ float g_c0[BROWS * HDIM], g_c1[BROWS * HDIM];
__device__ unsigned g_cntA[NGRP * 32];   // arrive/wait epoch counters (line-padded)
__device__ unsigned g_cntB[NGRP * 32];
__device__ unsigned g_gc[NGRP * 32];     // legacy rendezvous for end-of-launch reset
__device__ unsigned g_gg[NGRP * 32];

extern __shared__ uint32_t dynsmem[];

// ---------- helpers ----------
__device__ __forceinline__ uint32_t pack2(__nv_bfloat16 a, __nv_bfloat16 b) {
    return (uint32_t)__bfloat16_as_ushort(a) | ((uint32_t)__bfloat16_as_ushort(b) << 16);
}
__device__ __forceinline__ void split_pack(float v0, float v1, uint32_t& hi, uint32_t& lo) {
    __nv_bfloat16 h0 = __float2bfloat16(v0);
    __nv_bfloat16 h1 = __float2bfloat16(v1);
    float r0 = v0 - __bfloat162float(h0);   // exact
    float r1 = v1 - __bfloat162float(h1);
    hi = pack2(h0, h1);
    lo = pack2(__float2bfloat16(r0), __float2bfloat16(r1));
}
__device__ __forceinline__ void cp16(uint32_t* dst, const uint32_t* src) {
    unsigned sa = (unsigned)__cvta_generic_to_shared(dst);
    asm volatile("cp.async.cg.shared.global [%0], [%1], 16;" :: "r"(sa), "l"(src));
}
__device__ __forceinline__ void ldsm_x4(uint32_t* r, uint32_t saddr) {
    asm volatile("ldmatrix.sync.aligned.m8n8.x4.shared.b16 {%0,%1,%2,%3}, [%4];"
        : "=r"(r[0]), "=r"(r[1]), "=r"(r[2]), "=r"(r[3]) : "r"(saddr));
}
__device__ __forceinline__ void ldsm_x2(uint32_t* r, uint32_t saddr) {
    asm volatile("ldmatrix.sync.aligned.m8n8.x2.shared.b16 {%0,%1}, [%2];"
        : "=r"(r[0]), "=r"(r[1]) : "r"(saddr));
}
__device__ __forceinline__ unsigned atom_add_acqrel(unsigned* p, unsigned v) {
    unsigned old;
    asm volatile("atom.add.acq_rel.gpu.u32 %0, [%1], %2;"
        : "=r"(old) : "l"(p), "r"(v) : "memory");
    return old;
}
__device__ __forceinline__ unsigned ld_acquire(const unsigned* p) {
    unsigned v;
    asm volatile("ld.acquire.gpu.u32 %0, [%1];" : "=r"(v) : "l"(p) : "memory");
    return v;
}

// Split-barrier primitives over the 8 CTAs of one m-tile group.
// arrive: release prior global writes (h/c state) + bump epoch counter.
// wait:   block until all 8 CTAs of the group posted the target epoch.
__device__ __forceinline__ void group_arrive(unsigned* cnt) {
    __syncthreads();                      // all threads' epilogue writes CTA-visible
    if (threadIdx.x == 0) atom_add_acqrel(cnt, 1u);
}
__device__ __forceinline__ void group_wait(unsigned* cnt, unsigned target) {
    __syncthreads();
    if (threadIdx.x == 0) {
        while (ld_acquire(cnt) < target) __nanosleep(32);
    }
    __syncthreads();
}

// Legacy full rendezvous — used once at kernel end to reset epoch counters
// (graph replay requires counters back at 0; g_gg is compared relatively, so
// its monotonic growth is replay-safe).
__device__ __forceinline__ void group_rendezvous(int grp) {
    __syncthreads();
    if (threadIdx.x == 0) {
        unsigned* cnt = &g_gc[grp * 32];
        unsigned* gen = &g_gg[grp * 32];
        unsigned g = ld_acquire(gen);
        unsigned old = atom_add_acqrel(cnt, 1u);
        if (old == GRPSZ - 1u) {
            atom_add_acqrel(cnt, (unsigned)(-GRPSZ));
            atom_add_acqrel(gen, 1u);
        } else {
            while (ld_acquire(gen) == g) __nanosleep(32);
        }
    }
    __syncthreads();
}

// ---------- prep kernels ----------
__global__ void prep_weights(const float* __restrict__ W0, const float* __restrict__ W1,
                             const float* __restrict__ W2, const float* __restrict__ W3) {
    int idx = blockIdx.x * blockDim.x + threadIdx.x;
    if (idx >= 4 * NW * HPAIR) return;
    int mat = idx / (NW * HPAIR);
    int rem = idx - mat * (NW * HPAIR);
    int n = rem / HPAIR;
    int p = rem - n * HPAIR;
    const float* W = (mat == 0) ? W0 : (mat == 1) ? W1 : (mat == 2) ? W2 : W3;
    int gate = n & 3, h = n >> 2;
    int k = p * 2;
    float v0 = 0.f, v1 = 0.f;
    if (h < HDIM) {
        const float* row = W + (size_t)(gate * HDIM + h) * HDIM;
        if (k < HDIM)     v0 = row[k];
        if (k + 1 < HDIM) v1 = row[k + 1];
    }
    uint32_t hi, lo;
    split_pack(v0, v1, hi, lo);
    g_WH[idx] = hi;
    g_WL[idx] = lo;
}

__global__ void prep_z(const float* __restrict__ z) {
    int idx = blockIdx.x * blockDim.x + threadIdx.x;
    if (idx >= PAIRSZ) return;
    int r = idx / HPAIR;
    int p = idx - r * HPAIR;
    int k = p * 2;
    float v0 = (k < HDIM) ? z[(size_t)r * HDIM + k] : 0.f;
    float v1 = (k + 1 < HDIM) ? z[(size_t)r * HDIM + k + 1] : 0.f;
    uint32_t hi, lo;
    split_pack(v0, v1, hi, lo);
    g_zH[idx] = hi;
    g_zL[idx] = lo;
}

// ---------- staging ----------
__device__ __forceinline__ void stage_A(
    uint32_t* sbuf,
    const uint32_t* __restrict__ aH, const uint32_t* __restrict__ aL,
    int mBase, int p0, int tid)
{
    uint32_t* AsH = sbuf;
    uint32_t* AsL = sbuf + 2560;
#pragma unroll
    for (int i = 0; i < 4; i++) {
        int s = tid + i * NTHREADS;              // 0..1023
        int r = (s >> 2) & (BM - 1);
        int q = s & 3;
        const uint32_t* src = (s < 512) ? aH : aL;
        uint32_t* dst = (s < 512) ? AsH : AsL;
        cp16(dst + r * SMS + q * 4, src + (size_t)(mBase + r) * HPAIR + p0 + q * 4);
    }
}
__device__ __forceinline__ void stage_B(
    uint32_t* sbuf,
    const uint32_t* __restrict__ bH, const uint32_t* __restrict__ bL,
    int nBase, int p0, int tid)
{
    uint32_t* BsH = sbuf + 5120;
    uint32_t* BsL = sbuf + 8320;
#pragma unroll
    for (int i = 0; i < 5; i++) {
        int s = tid + i * NTHREADS;              // 0..1279
        int sp = (s >= 640);
        int ss = sp ? s - 640 : s;
        int r = ss >> 2;
        int q = ss & 3;
        const uint32_t* src = sp ? bL : bH;
        uint32_t* dst = sp ? BsL : BsH;
        cp16(dst + r * SMS + q * 4, src + (size_t)(nBase + r) * HPAIR + p0 + q * 4);
    }
}

#define MMA3(ACC, AH, AL, BHI, BLO)                                              \
    asm volatile("mma.sync.aligned.m16n8k16.row.col.f32.bf16.bf16.f32 "          \
        "{%0,%1,%2,%3}, {%4,%5,%6,%7}, {%8,%9}, {%0,%1,%2,%3};\n"                \
        : "+f"(ACC[0]), "+f"(ACC[1]), "+f"(ACC[2]), "+f"(ACC[3])                 \
        : "r"(AH[0]), "r"(AH[1]), "r"(AH[2]), "r"(AH[3]),                        \
          "r"(BLO[0]), "r"(BLO[1]));                                             \
    asm volatile("mma.sync.aligned.m16n8k16.row.col.f32.bf16.bf16.f32 "          \
        "{%0,%1,%2,%3}, {%4,%5,%6,%7}, {%8,%9}, {%0,%1,%2,%3};\n"                \
        : "+f"(ACC[0]), "+f"(ACC[1]), "+f"(ACC[2]), "+f"(ACC[3])                 \
        : "r"(AL[0]), "r"(AL[1]), "r"(AL[2]), "r"(AL[3]),                        \
          "r"(BHI[0]), "r"(BHI[1]));                                             \
    asm volatile("mma.sync.aligned.m16n8k16.row.col.f32.bf16.bf16.f32 "          \
        "{%0,%1,%2,%3}, {%4,%5,%6,%7}, {%8,%9}, {%0,%1,%2,%3};\n"                \
        : "+f"(ACC[0]), "+f"(ACC[1]), "+f"(ACC[2]), "+f"(ACC[3])                 \
        : "r"(AH[0]), "r"(AH[1]), "r"(AH[2]), "r"(AH[3]),                        \
          "r"(BHI[0]), "r"(BHI[1]));

// Fragments via ldmatrix (conflict-free at SMS=20). Identical MMA order to
// the passing R12 kernel.
__device__ __forceinline__ void mma_tile(
    uint32_t sbase, float (*acc)[5][4], int warpM, int warpN, int lane)
{
    const uint32_t AsH = sbase;
    const uint32_t AsL = sbase + 2560 * 4;
    const uint32_t BsH = sbase + 5120 * 4;
    const uint32_t BsL = sbase + 8320 * 4;
    const int aRow = lane & 15;
    const int aK4  = (lane & 16) >> 2;          // 0 or 4 (uint32 units)
    const int bRow = (lane & 7) | ((lane & 16) >> 1);
    const int bK4  = (lane & 8) >> 1;           // 0 or 4
    const int bRow2 = lane & 7;                  // for x2 (lanes 0-15 used)
#pragma unroll
    for (int kk = 0; kk < 2; kk++) {
        const int ko2 = kk * 8;
        uint32_t bh[5][2], bl[5][2];
#pragma unroll
        for (int np = 0; np < 2; np++) {         // ni pairs (0,1) and (2,3)
            int nb = warpN * 40 + np * 16;
            uint32_t r4[4];
            ldsm_x4(r4, BsH + (uint32_t)(((nb + bRow) * SMS + ko2 + bK4) << 2));
            bh[2 * np][0] = r4[0]; bh[2 * np][1] = r4[1];
            bh[2 * np + 1][0] = r4[2]; bh[2 * np + 1][1] = r4[3];
            ldsm_x4(r4, BsL + (uint32_t)(((nb + bRow) * SMS + ko2 + bK4) << 2));
            bl[2 * np][0] = r4[0]; bl[2 * np][1] = r4[1];
            bl[2 * np + 1][0] = r4[2]; bl[2 * np + 1][1] = r4[3];
        }
        {
            int nb = warpN * 40 + 32;            // ni = 4
            ldsm_x2(bh[4], BsH + (uint32_t)(((nb + bRow2) * SMS + ko2 + bK4) << 2));
            ldsm_x2(bl[4], BsL + (uint32_t)(((nb + bRow2) * SMS + ko2 + bK4) << 2));
        }
#pragma unroll
        for (int mi = 0; mi < 4; mi++) {
            int rb = warpM * 64 + mi * 16;
            uint32_t aH[4], aL[4];
            ldsm_x4(aH, AsH + (uint32_t)(((rb + aRow) * SMS + ko2 + aK4) << 2));
            ldsm_x4(aL, AsL + (uint32_t)(((rb + aRow) * SMS + ko2 + aK4) << 2));
#pragma unroll
            for (int ni = 0; ni < 5; ni++) {
                MMA3(acc[mi][ni], aH, aL, bh[ni], bl[ni]);
            }
        }
    }
}

// One fused LSTM cell, recurrent-segment-first with the group wait between
// segments so the wait latency hides behind 10 k-tiles of independent MMAs.
// Buffer-0 B-half of the first staged tile is always pre-staged by the
// previous cell's tail (or the driver prologue).
__device__ void run_cell(
    uint32_t smbase,
    const uint32_t* __restrict__ rH, const uint32_t* __restrict__ rL,  // recurrent A (null at t=0)
    const uint32_t* __restrict__ WrH, const uint32_t* __restrict__ WrL,
    const uint32_t* __restrict__ xH, const uint32_t* __restrict__ xL,  // input A
    const uint32_t* __restrict__ WxH, const uint32_t* __restrict__ WxL,
    unsigned* waitCnt, unsigned waitTarget,
    const float* __restrict__ cprev, const float* bias_s,
    uint32_t* __restrict__ hpH, uint32_t* __restrict__ hpL,            // bf16-pair h out
    float* __restrict__ houtF, int hOutStride,                         // optional fp32 h
    float* __restrict__ cout,
    int mBase, int hb,
    const uint32_t* __restrict__ nxBH, const uint32_t* __restrict__ nxBL) // next-cell B tile0
{
    const int tid   = threadIdx.x;
    const int lane  = tid & 31;
    const int warp  = tid >> 5;
    const int warpM = warp >> 2;
    const int warpN = warp & 3;
    const int gId   = lane >> 2;
    const int tid4  = lane & 3;
    const int nBase = hb * 4;

    float acc[4][5][4];
#pragma unroll
    for (int a = 0; a < 4; a++)
#pragma unroll
        for (int b = 0; b < 5; b++)
#pragma unroll
            for (int c = 0; c < 4; c++) acc[a][b][c] = 0.f;

    if (rH) {
        // ---- segment 1: recurrent GEMM (inputs synced at the previous wait) ----
        stage_A(dynsmem, rH, rL, mBase, 0, tid);     // buf0; B pre-staged
        asm volatile("cp.async.commit_group;");
#pragma unroll 1
        for (int kt = 0; kt < NKT; kt++) {
            asm volatile("cp.async.wait_group 0;");
            __syncthreads();
            if (kt + 1 < NKT) {
                uint32_t* buf = dynsmem + (size_t)((kt + 1) & 1) * BUFU32;
                stage_A(buf, rH, rL, mBase, (kt + 1) * KPAIR, tid);
                stage_B(buf, WrH, WrL, nBase, (kt + 1) * KPAIR, tid);
                asm volatile("cp.async.commit_group;");
            } else {
                // barrier-independent: weights of input-segment tile0 -> buf0
                stage_B(dynsmem, WxH, WxL, nBase, 0, tid);
                asm volatile("cp.async.commit_group;");
            }
            mma_tile(smbase + (uint32_t)((kt & 1) * BUFU32 * 4), acc, warpM, warpN, lane);
        }
    }

    // ---- group wait: peers' fresh state needed from here on ----
    group_wait(waitCnt, waitTarget);
    stage_A(dynsmem, xH, xL, mBase, 0, tid);         // buf0 (B already staged)
    asm volatile("cp.async.commit_group;");

    // ---- segment 2: input GEMM ----
#pragma unroll 1
    for (int kt = 0; kt < NKT; kt++) {
        asm volatile("cp.async.wait_group 0;");
        __syncthreads();
        if (kt + 1 < NKT) {
            uint32_t* buf = dynsmem + (size_t)((kt + 1) & 1) * BUFU32;
            stage_A(buf, xH, xL, mBase, (kt + 1) * KPAIR, tid);
            stage_B(buf, WxH, WxL, nBase, (kt + 1) * KPAIR, tid);
            asm volatile("cp.async.commit_group;");
        } else if (nxBH) {
            // tail prefetch: next cell's first B tile -> buf0
            stage_B(dynsmem, nxBH, nxBL, nBase, 0, tid);
            asm volatile("cp.async.commit_group;");
        }
        mma_tile(smbase + (uint32_t)((kt & 1) * BUFU32 * 4), acc, warpM, warpN, lane);
    }

    // epilogue: assemble i,f,g,o per hidden unit via shfl_xor(1)
    __nv_bfloat16* hpH16 = (__nv_bfloat16*)hpH;
    __nv_bfloat16* hpL16 = (__nv_bfloat16*)hpL;
#pragma unroll
    for (int mi = 0; mi < 4; mi++) {
        const int row_r = mBase + warpM * 64 + mi * 16 + gId;
#pragma unroll
        for (int ni = 0; ni < 5; ni++) {
            float c0v = acc[mi][ni][0], c1v = acc[mi][ni][1];
            float c2v = acc[mi][ni][2], c3v = acc[mi][ni][3];
            float p0 = __shfl_xor_sync(0xffffffffu, c0v, 1);
            float p1 = __shfl_xor_sync(0xffffffffu, c1v, 1);
            float p2 = __shfl_xor_sync(0xffffffffu, c2v, 1);
            float p3 = __shfl_xor_sync(0xffffffffu, c3v, 1);

            const int hl = warpN * 10 + ni * 2 + (tid4 >> 1);
            const int h = hb + hl;
            float iraw, fraw, graw, oraw;
            int row;
            if ((tid4 & 1) == 0) {
                iraw = c0v; fraw = c1v; graw = p0; oraw = p1; row = row_r;
            } else {
                iraw = p2; fraw = p3; graw = c2v; oraw = c3v; row = row_r + 8;
            }
            if (h < HDIM) {
                iraw += bias_s[4 * hl + 0];
                fraw += bias_s[4 * hl + 1];
                graw += bias_s[4 * hl + 2];
                oraw += bias_s[4 * hl + 3];
                float ig = 1.f / (1.f + expf(-iraw));
                float fg = 1.f / (1.f + expf(-fraw));
                float gg = tanhf(graw);
                float og = 1.f / (1.f + expf(-oraw));
                float cp = cprev ? cprev[(size_t)row * HDIM + h] : 0.f;
                float cn = fg * cp + ig * gg;
                float hn = og * tanhf(cn);
                cout[(size_t)row * HDIM + h] = cn;
                __nv_bfloat16 hh = __float2bfloat16(hn);
                float rem = hn - __bfloat162float(hh);
                hpH16[(size_t)row * HPAD + h] = hh;
                hpL16[(size_t)row * HPAD + h] = __float2bfloat16(rem);
                if (houtF) houtF[(size_t)row * hOutStride + h] = hn;
            }
        }
    }
}

// ---------- persistent driver kernel ----------
__global__ __launch_bounds__(NTHREADS, 2) void lstm_persistent(
    const float* __restrict__ b_ih0, const float* __restrict__ b_hh0,
    const float* __restrict__ b_ih1, const float* __restrict__ b_hh1,
    float* __restrict__ out, int T)
{
    const int bid   = blockIdx.x;
    const int mBase = (bid >> 3) * BM;   // 32 m-tiles
    const int hb    = (bid & 7) * BH;    // 8 h-blocks
    const int grp   = bid >> 3;          // sync group = m-tile
    const int tid   = threadIdx.x;
    const int nBase = hb * 4;

    const uint32_t smbase = (uint32_t)__cvta_generic_to_shared(dynsmem);
    unsigned* cntA = &g_cntA[grp * 32];
    unsigned* cntB = &g_cntB[grp * 32];

    float* bias0 = (float*)(dynsmem + 2 * BUFU32);
    float* bias1 = bias0 + BNC;
    if (tid < BNC) {
        int gate = tid & 3, hl = tid >> 2, h = hb + hl;
        bias0[tid] = (h < HDIM) ? (b_ih0[gate * HDIM + h] + b_hh0[gate * HDIM + h]) : 0.f;
        bias1[tid] = (h < HDIM) ? (b_ih1[gate * HDIM + h] + b_hh1[gate * HDIM + h]) : 0.f;
    }
    __syncthreads();

    const int WSTEP = NW * HPAIR;

    // prologue prefetch: L0[0] has no recurrent segment; its first tile is
    // the input segment (z, Wih0) -> pre-stage Wih0 B tile0 into buf0.
    stage_B(dynsmem, g_WH + 0 * WSTEP, g_WL + 0 * WSTEP, nBase, 0, tid);
    asm volatile("cp.async.commit_group;");

#pragma unroll 1
    for (int t = 0; t < T; t++) {
        const int wr = t & 1, rd = (t + 1) & 1;

        // ---- layer 0: seg1 = Whh0·h0[t-1], wait_A(8t) [o[t-1]], seg2 = Wih0·x ----
        {
            const uint32_t* rH = t ? g_h0H + (size_t)rd * PAIRSZ : nullptr;
            const uint32_t* rL = t ? g_h0L + (size_t)rd * PAIRSZ : nullptr;
            const uint32_t* xH = t ? g_oH + (size_t)rd * PAIRSZ : g_zH;
            const uint32_t* xL = t ? g_oL + (size_t)rd * PAIRSZ : g_zL;
            // next cell (L1[t]): first staged B = Whh1 (t>0) or Wih1 (t==0)
            const uint32_t* nxH = t ? g_WH + 3 * WSTEP : g_WH + 2 * WSTEP;
            const uint32_t* nxL = t ? g_WL + 3 * WSTEP : g_WL + 2 * WSTEP;
            run_cell(smbase,
                     rH, rL, g_WH + 1 * WSTEP, g_WL + 1 * WSTEP,
                     xH, xL, g_WH + 0 * WSTEP, g_WL + 0 * WSTEP,
                     cntA, 8u * (unsigned)t,
                     t ? g_c0 : nullptr, bias0,
                     g_h0H + (size_t)wr * PAIRSZ, g_h0L + (size_t)wr * PAIRSZ,
                     nullptr, 0, g_c0, mBase, hb, nxH, nxL);
            group_arrive(cntB);            // h0[t] published
        }

        // ---- layer 1: seg1 = Whh1·o[t-1], wait_B(8(t+1)) [h0[t]], seg2 = Wih1·h0[t] ----
        {
            const uint32_t* rH = t ? g_oH + (size_t)rd * PAIRSZ : nullptr;
            const uint32_t* rL = t ? g_oL + (size_t)rd * PAIRSZ : nullptr;
            // next cell (L0[t+1]): first staged B = Whh0; none after the last step
            const uint32_t* nxH = (t + 1 < T) ? g_WH + 1 * WSTEP : nullptr;
            const uint32_t* nxL = (t + 1 < T) ? g_WL + 1 * WSTEP : nullptr;
            run_cell(smbase,
                     rH, rL, g_WH + 3 * WSTEP, g_WL + 3 * WSTEP,
                     g_h0H + (size_t)wr * PAIRSZ, g_h0L + (size_t)wr * PAIRSZ,
                     g_WH + 2 * WSTEP, g_WL + 2 * WSTEP,
                     cntB, 8u * (unsigned)(t + 1),
                     t ? g_c1 : nullptr, bias1,
                     g_oH + (size_t)wr * PAIRSZ, g_oL + (size_t)wr * PAIRSZ,
                     out + (size_t)t * HDIM, T * HDIM, g_c1, mBase, hb, nxH, nxL);
            group_arrive(cntA);            // o[t] published
        }
    }

    // reset epoch counters for graph replay (all arrivals done after rendezvous)
    group_rendezvous(grp);
    if ((bid & 7) == 0 && tid == 0) {
        atom_add_acqrel(cntA, (unsigned)(-(8u * (unsigned)T)));
        atom_add_acqrel(cntB, (unsigned)(-(8u * (unsigned)T)));
    }
}

extern "C" void kernel_launch(void* const* d_in, const int* in_sizes, int n_in,
                              void* d_out, int out_size)
{
    const float* z     = (const float*)d_in[0];
    const float* W_ih0 = (const float*)d_in[1];
    const float* W_hh0 = (const float*)d_in[2];
    const float* b_ih0 = (const float*)d_in[3];
    const float* b_hh0 = (const float*)d_in[4];
    const float* W_ih1 = (const float*)d_in[5];
    const float* W_hh1 = (const float*)d_in[6];
    const float* b_ih1 = (const float*)d_in[7];
    const float* b_hh1 = (const float*)d_in[8];
    float* out = (float*)d_out;

    const int Bsz = in_sizes[0] / HDIM;      // 4096
    const int T   = out_size / (Bsz * HDIM); // 64
    const int WSTEP = NW * HPAIR;

    prep_weights<<<(4 * WSTEP + 255) / 256, 256>>>(W_ih0, W_hh0, W_ih1, W_hh1);
    prep_z<<<(PAIRSZ + 255) / 256, 256>>>(z);

    static int attr_done = 0;
    if (!attr_done) {
        cudaFuncSetAttribute(lstm_persistent,
                             cudaFuncAttributeMaxDynamicSharedMemorySize,
                             SMEM_U32 * 4);
        attr_done = 1;
    }
    lstm_persistent<<<NGRP * GRPSZ, NTHREADS, SMEM_U32 * 4>>>(b_ih0, b_hh0, b_ih1, b_hh1,
                                                              out, T);
}

// round 14
// speedup vs baseline: 1.7448x; 1.0034x over previous
#include <cuda_runtime.h>
#include <cuda_bf16.h>
#include <cstdint>

// ---- problem constants ----
#define HDIM 300
#define HPAD 320          // padded k extent (bf16 elems)
#define HPAIR 160         // uint32 (bf16x2) pairs per row
#define BROWS 4096
#define BM 128            // batch rows per CTA
#define BH 40             // hidden units per CTA -> 8 h-blocks
#define BNC 160           // gate-columns per CTA (4*BH)
#define KPAIR 16          // k-pairs per tile (BK=32)
#define SMS 20            // smem row stride in uint32 (16 + 4 pad) -> ldmatrix conflict-free
#define NKT 10            // k-tiles per GEMM segment
#define NTHREADS 256
#define NW 1280           // padded row-permuted weight rows
#define PAIRSZ (BROWS * HPAIR)
#define NGRP 32           // one independent sync group per m-tile
#define GRPSZ 8           // 8 h-block CTAs per group
// dynamic smem layout (uint32 units)
#define BUFU32 11520      // AsH(2560)+AsL(2560)+BsH(3200)+BsL(3200)
#define SMEM_U32 (2 * BUFU32 + 2 * BNC)

// ---- device scratch (no allocation allowed) ----
__device__ uint32_t g_zH[PAIRSZ], g_zL[PAIRSZ];
__device__ uint32_t g_h0H[2 * PAIRSZ], g_h0L[2 * PAIRSZ];   // ping-pong layer0 h
__device__ uint32_t g_oH[2 * PAIRSZ], g_oL[2 * PAIRSZ];     // ping-pong layer1 h
__device__ uint32_t g_WH[4 * NW * HPAIR], g_WL[4 * NW * HPAIR]; // Wih0,Whh0,Wih1,Whh1
__device__ float g_c0[BROWS * HDIM], g_c1[BROWS * HDIM];
__device__ unsigned g_cntA[NGRP * 32];   // arrive/wait epoch counters (line-padded)
__device__ unsigned g_cntB[NGRP * 32];
__device__ unsigned g_gc[NGRP * 32];     // rendezvous for end-of-launch reset
__device__ unsigned g_gg[NGRP * 32];

extern __shared__ uint32_t dynsmem[];

// ---------- helpers ----------
__device__ __forceinline__ uint32_t pack2(__nv_bfloat16 a, __nv_bfloat16 b) {
    return (uint32_t)__bfloat16_as_ushort(a) | ((uint32_t)__bfloat16_as_ushort(b) << 16);
}
__device__ __forceinline__ void split_pack(float v0, float v1, uint32_t& hi, uint32_t& lo) {
    __nv_bfloat16 h0 = __float2bfloat16(v0);
    __nv_bfloat16 h1 = __float2bfloat16(v1);
    float r0 = v0 - __bfloat162float(h0);   // exact
    float r1 = v1 - __bfloat162float(h1);
    hi = pack2(h0, h1);
    lo = pack2(__float2bfloat16(r0), __float2bfloat16(r1));
}
__device__ __forceinline__ void cp16(uint32_t* dst, const uint32_t* src) {
    unsigned sa = (unsigned)__cvta_generic_to_shared(dst);
    asm volatile("cp.async.cg.shared.global [%0], [%1], 16;" :: "r"(sa), "l"(src));
}
__device__ __forceinline__ void ldsm_x4(uint32_t* r, uint32_t saddr) {
    asm volatile("ldmatrix.sync.aligned.m8n8.x4.shared.b16 {%0,%1,%2,%3}, [%4];"
        : "=r"(r[0]), "=r"(r[1]), "=r"(r[2]), "=r"(r[3]) : "r"(saddr));
}
__device__ __forceinline__ void ldsm_x2(uint32_t* r, uint32_t saddr) {
    asm volatile("ldmatrix.sync.aligned.m8n8.x2.shared.b16 {%0,%1}, [%2];"
        : "=r"(r[0]), "=r"(r[1]) : "r"(saddr));
}
__device__ __forceinline__ unsigned atom_add_acqrel(unsigned* p, unsigned v) {
    unsigned old;
    asm volatile("atom.add.acq_rel.gpu.u32 %0, [%1], %2;"
        : "=r"(old) : "l"(p), "r"(v) : "memory");
    return old;
}
__device__ __forceinline__ unsigned ld_acquire(const unsigned* p) {
    unsigned v;
    asm volatile("ld.acquire.gpu.u32 %0, [%1];" : "=r"(v) : "l"(p) : "memory");
    return v;
}

// Split-barrier primitives over the 8 CTAs of one m-tile group.
__device__ __forceinline__ void group_arrive(unsigned* cnt) {
    __syncthreads();                      // all threads' epilogue writes CTA-visible
    if (threadIdx.x == 0) atom_add_acqrel(cnt, 1u);
}
__device__ __forceinline__ void group_wait(unsigned* cnt, unsigned target) {
    __syncthreads();
    if (threadIdx.x == 0) {
        while (ld_acquire(cnt) < target) __nanosleep(32);
    }
    __syncthreads();
}

// Full rendezvous — once at kernel end to reset epoch counters for graph replay.
__device__ __forceinline__ void group_rendezvous(int grp) {
    __syncthreads();
    if (threadIdx.x == 0) {
        unsigned* cnt = &g_gc[grp * 32];
        unsigned* gen = &g_gg[grp * 32];
        unsigned g = ld_acquire(gen);
        unsigned old = atom_add_acqrel(cnt, 1u);
        if (old == GRPSZ - 1u) {
            atom_add_acqrel(cnt, (unsigned)(-GRPSZ));
            atom_add_acqrel(gen, 1u);
        } else {
            while (ld_acquire(gen) == g) __nanosleep(32);
        }
    }
    __syncthreads();
}

// ---------- prep kernels ----------
__global__ void prep_weights(const float* __restrict__ W0, const float* __restrict__ W1,
                             const float* __restrict__ W2, const float* __restrict__ W3) {
    int idx = blockIdx.x * blockDim.x + threadIdx.x;
    if (idx >= 4 * NW * HPAIR) return;
    int mat = idx / (NW * HPAIR);
    int rem = idx - mat * (NW * HPAIR);
    int n = rem / HPAIR;
    int p = rem - n * HPAIR;
    const float* W = (mat == 0) ? W0 : (mat == 1) ? W1 : (mat == 2) ? W2 : W3;
    int gate = n & 3, h = n >> 2;
    int k = p * 2;
    float v0 = 0.f, v1 = 0.f;
    if (h < HDIM) {
        const float* row = W + (size_t)(gate * HDIM + h) * HDIM;
        if (k < HDIM)     v0 = row[k];
        if (k + 1 < HDIM) v1 = row[k + 1];
    }
    uint32_t hi, lo;
    split_pack(v0, v1, hi, lo);
    g_WH[idx] = hi;
    g_WL[idx] = lo;
}

__global__ void prep_z(const float* __restrict__ z) {
    int idx = blockIdx.x * blockDim.x + threadIdx.x;
    if (idx >= PAIRSZ) return;
    int r = idx / HPAIR;
    int p = idx - r * HPAIR;
    int k = p * 2;
    float v0 = (k < HDIM) ? z[(size_t)r * HDIM + k] : 0.f;
    float v1 = (k + 1 < HDIM) ? z[(size_t)r * HDIM + k + 1] : 0.f;
    uint32_t hi, lo;
    split_pack(v0, v1, hi, lo);
    g_zH[idx] = hi;
    g_zL[idx] = lo;
}

// ---------- staging ----------
__device__ __forceinline__ void stage_A(
    uint32_t* sbuf,
    const uint32_t* __restrict__ aH, const uint32_t* __restrict__ aL,
    int mBase, int p0, int tid)
{
    uint32_t* AsH = sbuf;
    uint32_t* AsL = sbuf + 2560;
#pragma unroll
    for (int i = 0; i < 4; i++) {
        int s = tid + i * NTHREADS;              // 0..1023
        int r = (s >> 2) & (BM - 1);
        int q = s & 3;
        const uint32_t* src = (s < 512) ? aH : aL;
        uint32_t* dst = (s < 512) ? AsH : AsL;
        cp16(dst + r * SMS + q * 4, src + (size_t)(mBase + r) * HPAIR + p0 + q * 4);
    }
}
__device__ __forceinline__ void stage_B(
    uint32_t* sbuf,
    const uint32_t* __restrict__ bH, const uint32_t* __restrict__ bL,
    int nBase, int p0, int tid)
{
    uint32_t* BsH = sbuf + 5120;
    uint32_t* BsL = sbuf + 8320;
#pragma unroll
    for (int i = 0; i < 5; i++) {
        int s = tid + i * NTHREADS;              // 0..1279
        int sp = (s >= 640);
        int ss = sp ? s - 640 : s;
        int r = ss >> 2;
        int q = ss & 3;
        const uint32_t* src = sp ? bL : bH;
        uint32_t* dst = sp ? BsL : BsH;
        cp16(dst + r * SMS + q * 4, src + (size_t)(nBase + r) * HPAIR + p0 + q * 4);
    }
}

#define MMA3(ACC, AH, AL, BHI, BLO)                                              \
    asm volatile("mma.sync.aligned.m16n8k16.row.col.f32.bf16.bf16.f32 "          \
        "{%0,%1,%2,%3}, {%4,%5,%6,%7}, {%8,%9}, {%0,%1,%2,%3};\n"                \
        : "+f"(ACC[0]), "+f"(ACC[1]), "+f"(ACC[2]), "+f"(ACC[3])                 \
        : "r"(AH[0]), "r"(AH[1]), "r"(AH[2]), "r"(AH[3]),                        \
          "r"(BLO[0]), "r"(BLO[1]));                                             \
    asm volatile("mma.sync.aligned.m16n8k16.row.col.f32.bf16.bf16.f32 "          \
        "{%0,%1,%2,%3}, {%4,%5,%6,%7}, {%8,%9}, {%0,%1,%2,%3};\n"                \
        : "+f"(ACC[0]), "+f"(ACC[1]), "+f"(ACC[2]), "+f"(ACC[3])                 \
        : "r"(AL[0]), "r"(AL[1]), "r"(AL[2]), "r"(AL[3]),                        \
          "r"(BHI[0]), "r"(BHI[1]));                                             \
    asm volatile("mma.sync.aligned.m16n8k16.row.col.f32.bf16.bf16.f32 "          \
        "{%0,%1,%2,%3}, {%4,%5,%6,%7}, {%8,%9}, {%0,%1,%2,%3};\n"                \
        : "+f"(ACC[0]), "+f"(ACC[1]), "+f"(ACC[2]), "+f"(ACC[3])                 \
        : "r"(AH[0]), "r"(AH[1]), "r"(AH[2]), "r"(AH[3]),                        \
          "r"(BHI[0]), "r"(BHI[1]));

// Fragments via ldmatrix (conflict-free at SMS=20). Identical MMA order to R13.
__device__ __forceinline__ void mma_tile(
    uint32_t sbase, float (*acc)[5][4], int warpM, int warpN, int lane)
{
    const uint32_t AsH = sbase;
    const uint32_t AsL = sbase + 2560 * 4;
    const uint32_t BsH = sbase + 5120 * 4;
    const uint32_t BsL = sbase + 8320 * 4;
    const int aRow = lane & 15;
    const int aK4  = (lane & 16) >> 2;          // 0 or 4 (uint32 units)
    const int bRow = (lane & 7) | ((lane & 16) >> 1);
    const int bK4  = (lane & 8) >> 1;           // 0 or 4
    const int bRow2 = lane & 7;                  // for x2 (lanes 0-15 used)
#pragma unroll
    for (int kk = 0; kk < 2; kk++) {
        const int ko2 = kk * 8;
        uint32_t bh[5][2], bl[5][2];
#pragma unroll
        for (int np = 0; np < 2; np++) {         // ni pairs (0,1) and (2,3)
            int nb = warpN * 40 + np * 16;
            uint32_t r4[4];
            ldsm_x4(r4, BsH + (uint32_t)(((nb + bRow) * SMS + ko2 + bK4) << 2));
            bh[2 * np][0] = r4[0]; bh[2 * np][1] = r4[1];
            bh[2 * np + 1][0] = r4[2]; bh[2 * np + 1][1] = r4[3];
            ldsm_x4(r4, BsL + (uint32_t)(((nb + bRow) * SMS + ko2 + bK4) << 2));
            bl[2 * np][0] = r4[0]; bl[2 * np][1] = r4[1];
            bl[2 * np + 1][0] = r4[2]; bl[2 * np + 1][1] = r4[3];
        }
        {
            int nb = warpN * 40 + 32;            // ni = 4
            ldsm_x2(bh[4], BsH + (uint32_t)(((nb + bRow2) * SMS + ko2 + bK4) << 2));
            ldsm_x2(bl[4], BsL + (uint32_t)(((nb + bRow2) * SMS + ko2 + bK4) << 2));
        }
#pragma unroll
        for (int mi = 0; mi < 4; mi++) {
            int rb = warpM * 64 + mi * 16;
            uint32_t aH[4], aL[4];
            ldsm_x4(aH, AsH + (uint32_t)(((rb + aRow) * SMS + ko2 + aK4) << 2));
            ldsm_x4(aL, AsL + (uint32_t)(((rb + aRow) * SMS + ko2 + aK4) << 2));
#pragma unroll
            for (int ni = 0; ni < 5; ni++) {
                MMA3(acc[mi][ni], aH, aL, bh[ni], bl[ni]);
            }
        }
    }
}

// One fused LSTM cell: single 20-tile pipeline (recurrent tiles 0-9, input
// tiles 10-19) with the group wait embedded in tile-10's staging slot, and a
// tail prefetch of the NEXT cell's tile 0 (covered by this cell's epilogue).
// Steady-state cells (rH != null) start with tile 0 already in flight in buf0.
__device__ void run_cell(
    uint32_t smbase,
    const uint32_t* __restrict__ rH, const uint32_t* __restrict__ rL,  // recurrent A (null at t=0)
    const uint32_t* __restrict__ WrH, const uint32_t* __restrict__ WrL,
    const uint32_t* __restrict__ xH, const uint32_t* __restrict__ xL,  // input A
    const uint32_t* __restrict__ WxH, const uint32_t* __restrict__ WxL,
    unsigned* waitCnt, unsigned waitTarget,
    const float* __restrict__ cprev, const float* bias_s,
    uint32_t* __restrict__ hpH, uint32_t* __restrict__ hpL,            // bf16-pair h out
    float* __restrict__ houtF, int hOutStride,                         // optional fp32 h
    float* __restrict__ cout,
    int mBase, int hb,
    const uint32_t* __restrict__ nxAH, const uint32_t* __restrict__ nxAL, // next-cell tile0 A
    const uint32_t* __restrict__ nxBH, const uint32_t* __restrict__ nxBL) // next-cell tile0 B
{
    const int tid   = threadIdx.x;
    const int lane  = tid & 31;
    const int warp  = tid >> 5;
    const int warpM = warp >> 2;
    const int warpN = warp & 3;
    const int gId   = lane >> 2;
    const int tid4  = lane & 3;
    const int nBase = hb * 4;

    float acc[4][5][4];
#pragma unroll
    for (int a = 0; a < 4; a++)
#pragma unroll
        for (int b = 0; b < 5; b++)
#pragma unroll
            for (int c = 0; c < 4; c++) acc[a][b][c] = 0.f;

    const int kStart = rH ? 0 : NKT;

    if (!rH) {
        // t=0 cells: no recurrent segment; wait then stage input tile0 A
        // (B was pre-staged into buf0 by the driver / previous cell's tail).
        group_wait(waitCnt, waitTarget);
        stage_A(dynsmem, xH, xL, mBase, 0, tid);
        asm volatile("cp.async.commit_group;");
    }

#pragma unroll 1
    for (int kt = kStart; kt < 2 * NKT; kt++) {
        asm volatile("cp.async.wait_group 0;");
        __syncthreads();   // tile kt landed; all warps done with tile kt-1
        int k2 = kt + 1;
        if (k2 < 2 * NKT) {
            if (k2 == NKT) group_wait(waitCnt, waitTarget);  // seg boundary
            const uint32_t *sAH, *sAL, *sBH, *sBL;
            int p0;
            if (k2 < NKT) { sAH = rH; sAL = rL; sBH = WrH; sBL = WrL; p0 = k2 * KPAIR; }
            else          { sAH = xH; sAL = xL; sBH = WxH; sBL = WxL; p0 = (k2 - NKT) * KPAIR; }
            uint32_t* buf = dynsmem + (size_t)(k2 & 1) * BUFU32;
            stage_A(buf, sAH, sAL, mBase, p0, tid);
            stage_B(buf, sBH, sBL, nBase, p0, tid);
            asm volatile("cp.async.commit_group;");
        } else {
            // tail: prefetch next cell's tile0 into buf0 (epilogue covers it)
            int any = 0;
            if (nxBH) { stage_B(dynsmem, nxBH, nxBL, nBase, 0, tid); any = 1; }
            if (nxAH) { stage_A(dynsmem, nxAH, nxAL, mBase, 0, tid); any = 1; }
            if (any) asm volatile("cp.async.commit_group;");
        }
        mma_tile(smbase + (uint32_t)((kt & 1) * BUFU32 * 4), acc, warpM, warpN, lane);
    }

    // epilogue: assemble i,f,g,o per hidden unit via shfl_xor(1); fast-math gates
    __nv_bfloat16* hpH16 = (__nv_bfloat16*)hpH;
    __nv_bfloat16* hpL16 = (__nv_bfloat16*)hpL;
#pragma unroll
    for (int mi = 0; mi < 4; mi++) {
        const int row_r = mBase + warpM * 64 + mi * 16 + gId;
#pragma unroll
        for (int ni = 0; ni < 5; ni++) {
            float c0v = acc[mi][ni][0], c1v = acc[mi][ni][1];
            float c2v = acc[mi][ni][2], c3v = acc[mi][ni][3];
            float p0 = __shfl_xor_sync(0xffffffffu, c0v, 1);
            float p1 = __shfl_xor_sync(0xffffffffu, c1v, 1);
            float p2 = __shfl_xor_sync(0xffffffffu, c2v, 1);
            float p3 = __shfl_xor_sync(0xffffffffu, c3v, 1);

            const int hl = warpN * 10 + ni * 2 + (tid4 >> 1);
            const int h = hb + hl;
            float iraw, fraw, graw, oraw;
            int row;
            if ((tid4 & 1) == 0) {
                iraw = c0v; fraw = c1v; graw = p0; oraw = p1; row = row_r;
            } else {
                iraw = p2; fraw = p3; graw = c2v; oraw = c3v; row = row_r + 8;
            }
            if (h < HDIM) {
                iraw += bias_s[4 * hl + 0];
                fraw += bias_s[4 * hl + 1];
                graw += bias_s[4 * hl + 2];
                oraw += bias_s[4 * hl + 3];
                float ig = __fdividef(1.f, 1.f + __expf(-iraw));
                float fg = __fdividef(1.f, 1.f + __expf(-fraw));
                float gg = 1.f - __fdividef(2.f, __expf(2.f * graw) + 1.f);
                float og = __fdividef(1.f, 1.f + __expf(-oraw));
                float cp = cprev ? cprev[(size_t)row * HDIM + h] : 0.f;
                float cn = fg * cp + ig * gg;
                float hn = og * (1.f - __fdividef(2.f, __expf(2.f * cn) + 1.f));
                cout[(size_t)row * HDIM + h] = cn;
                __nv_bfloat16 hh = __float2bfloat16(hn);
                float rem = hn - __bfloat162float(hh);
                hpH16[(size_t)row * HPAD + h] = hh;
                hpL16[(size_t)row * HPAD + h] = __float2bfloat16(rem);
                if (houtF) houtF[(size_t)row * hOutStride + h] = hn;
            }
        }
    }
}

// ---------- persistent driver kernel ----------
__global__ __launch_bounds__(NTHREADS, 2) void lstm_persistent(
    const float* __restrict__ b_ih0, const float* __restrict__ b_hh0,
    const float* __restrict__ b_ih1, const float* __restrict__ b_hh1,
    float* __restrict__ out, int T)
{
    const int bid   = blockIdx.x;
    const int mBase = (bid >> 3) * BM;   // 32 m-tiles
    const int hb    = (bid & 7) * BH;    // 8 h-blocks
    const int grp   = bid >> 3;          // sync group = m-tile
    const int tid   = threadIdx.x;
    const int nBase = hb * 4;

    const uint32_t smbase = (uint32_t)__cvta_generic_to_shared(dynsmem);
    unsigned* cntA = &g_cntA[grp * 32];
    unsigned* cntB = &g_cntB[grp * 32];

    float* bias0 = (float*)(dynsmem + 2 * BUFU32);
    float* bias1 = bias0 + BNC;
    if (tid < BNC) {
        int gate = tid & 3, hl = tid >> 2, h = hb + hl;
        bias0[tid] = (h < HDIM) ? (b_ih0[gate * HDIM + h] + b_hh0[gate * HDIM + h]) : 0.f;
        bias1[tid] = (h < HDIM) ? (b_ih1[gate * HDIM + h] + b_hh1[gate * HDIM + h]) : 0.f;
    }
    __syncthreads();

    const int WSTEP = NW * HPAIR;

    // prologue prefetch: L0[0]'s first tile is the input segment (z, Wih0)
    stage_B(dynsmem, g_WH + 0 * WSTEP, g_WL + 0 * WSTEP, nBase, 0, tid);
    asm volatile("cp.async.commit_group;");

#pragma unroll 1
    for (int t = 0; t < T; t++) {
        const int wr = t & 1, rd = (t + 1) & 1;

        // ---- layer 0 ----
        if (t == 0) {
            // no recurrent seg; next cell L1[0]: only B prefetchable (h0[0] made here)
            run_cell(smbase,
                     nullptr, nullptr, nullptr, nullptr,
                     g_zH, g_zL, g_WH + 0 * WSTEP, g_WL + 0 * WSTEP,
                     cntA, 0u,
                     nullptr, bias0,
                     g_h0H, g_h0L, nullptr, 0, g_c0, mBase, hb,
                     nullptr, nullptr,
                     g_WH + 2 * WSTEP, g_WL + 2 * WSTEP);
        } else {
            // next cell L1[t]: seg1 A = o[t-1] (synced at our boundary wait)
            run_cell(smbase,
                     g_h0H + (size_t)rd * PAIRSZ, g_h0L + (size_t)rd * PAIRSZ,
                     g_WH + 1 * WSTEP, g_WL + 1 * WSTEP,
                     g_oH + (size_t)rd * PAIRSZ, g_oL + (size_t)rd * PAIRSZ,
                     g_WH + 0 * WSTEP, g_WL + 0 * WSTEP,
                     cntA, 8u * (unsigned)t,
                     g_c0, bias0,
                     g_h0H + (size_t)wr * PAIRSZ, g_h0L + (size_t)wr * PAIRSZ,
                     nullptr, 0, g_c0, mBase, hb,
                     g_oH + (size_t)rd * PAIRSZ, g_oL + (size_t)rd * PAIRSZ,
                     g_WH + 3 * WSTEP, g_WL + 3 * WSTEP);
        }
        group_arrive(cntB);            // h0[t] published

        // ---- layer 1 (writes fp32 h into output slice t) ----
        if (t == 0) {
            // no recurrent seg; next cell L0[1]: seg1 A = h0[0] (synced at our wait)
            run_cell(smbase,
                     nullptr, nullptr, nullptr, nullptr,
                     g_h0H, g_h0L, g_WH + 2 * WSTEP, g_WL + 2 * WSTEP,
                     cntB, 8u,
                     nullptr, bias1,
                     g_oH, g_oL, out, T * HDIM, g_c1, mBase, hb,
                     g_h0H, g_h0L,
                     g_WH + 1 * WSTEP, g_WL + 1 * WSTEP);
        } else {
            const int last = (t + 1 >= T);
            run_cell(smbase,
                     g_oH + (size_t)rd * PAIRSZ, g_oL + (size_t)rd * PAIRSZ,
                     g_WH + 3 * WSTEP, g_WL + 3 * WSTEP,
                     g_h0H + (size_t)wr * PAIRSZ, g_h0L + (size_t)wr * PAIRSZ,
                     g_WH + 2 * WSTEP, g_WL + 2 * WSTEP,
                     cntB, 8u * (unsigned)(t + 1),
                     g_c1, bias1,
                     g_oH + (size_t)wr * PAIRSZ, g_oL + (size_t)wr * PAIRSZ,
                     out + (size_t)t * HDIM, T * HDIM, g_c1, mBase, hb,
                     last ? nullptr : g_h0H + (size_t)wr * PAIRSZ,
                     last ? nullptr : g_h0L + (size_t)wr * PAIRSZ,
                     last ? nullptr : g_WH + 1 * WSTEP,
                     last ? nullptr : g_WL + 1 * WSTEP);
        }
        group_arrive(cntA);            // o[t] published
    }

    // reset epoch counters for graph replay
    group_rendezvous(grp);
    if ((bid & 7) == 0 && tid == 0) {
        atom_add_acqrel(cntA, (unsigned)(-(8u * (unsigned)T)));
        atom_add_acqrel(cntB, (unsigned)(-(8u * (unsigned)T)));
    }
}

extern "C" void kernel_launch(void* const* d_in, const int* in_sizes, int n_in,
                              void* d_out, int out_size)
{
    const float* z     = (const float*)d_in[0];
    const float* W_ih0 = (const float*)d_in[1];
    const float* W_hh0 = (const float*)d_in[2];
    const float* b_ih0 = (const float*)d_in[3];
    const float* b_hh0 = (const float*)d_in[4];
    const float* W_ih1 = (const float*)d_in[5];
    const float* W_hh1 = (const float*)d_in[6];
    const float* b_ih1 = (const float*)d_in[7];
    const float* b_hh1 = (const float*)d_in[8];
    float* out = (float*)d_out;

    const int Bsz = in_sizes[0] / HDIM;      // 4096
    const int T   = out_size / (Bsz * HDIM); // 64
    const int WSTEP = NW * HPAIR;

    prep_weights<<<(4 * WSTEP + 255) / 256, 256>>>(W_ih0, W_hh0, W_ih1, W_hh1);
    prep_z<<<(PAIRSZ + 255) / 256, 256>>>(z);

    static int attr_done = 0;
    if (!attr_done) {
        cudaFuncSetAttribute(lstm_persistent,
                             cudaFuncAttributeMaxDynamicSharedMemorySize,
                             SMEM_U32 * 4);
        attr_done = 1;
    }
    lstm_persistent<<<NGRP * GRPSZ, NTHREADS, SMEM_U32 * 4>>>(b_ih0, b_hh0, b_ih1, b_hh1,
                                                              out, T);
}

// round 15
// speedup vs baseline: 2.1703x; 1.2438x over previous
#include <cuda_runtime.h>
#include <cuda_bf16.h>
#include <cstdint>

// ---- problem constants ----
#define HDIM 300
#define HPAD 320          // padded k extent (elements)
#define HU32 320          // u32 (tf32) per activation/weight row
#define BROWS 4096
#define BM 128            // batch rows per CTA
#define BH 40             // hidden units per CTA -> 8 h-blocks
#define BNC 160           // gate-columns per CTA (4*BH)
#define BK 32             // k elements per tile
#define SMS 36            // smem row stride in u32 (32 + 4 pad) -> ldmatrix conflict-free
#define NKT 10            // k-tiles per GEMM segment
#define NTHREADS 256
#define NW 1280           // padded row-permuted weight rows
#define ASTRIDE (BROWS * HU32)
#define WSTEP (NW * HU32)
#define NGRP 32           // one independent sync group per m-tile
#define GRPSZ 8           // 8 h-block CTAs per group
// dynamic smem layout (u32 units)
#define A_U32 4608        // 128 * 36
#define BUFU32 10368      // A(4608) + B(160*36=5760)
#define SMEM_U32 (2 * BUFU32 + 2 * BNC)

// ---- device scratch (no allocation allowed) ----
__device__ uint32_t g_zT[ASTRIDE];
__device__ uint32_t g_h0T[2 * ASTRIDE];       // ping-pong layer0 h (tf32 words)
__device__ uint32_t g_oT[2 * ASTRIDE];        // ping-pong layer1 h
__device__ uint32_t g_WT[4 * WSTEP];          // Wih0,Whh0,Wih1,Whh1 (row-permuted tf32)
__device__ float g_c0[BROWS * HDIM], g_c1[BROWS * HDIM];
__device__ unsigned g_cntA[NGRP * 32];        // arrive/wait epoch counters (line-padded)
__device__ unsigned g_cntB[NGRP * 32];
__device__ unsigned g_gc[NGRP * 32];          // rendezvous for end-of-launch reset
__device__ unsigned g_gg[NGRP * 32];

extern __shared__ uint32_t dynsmem[];

// ---------- helpers ----------
__device__ __forceinline__ uint32_t f2tf32(float f) {
    uint32_t u;
    asm("cvt.rna.tf32.f32 %0, %1;" : "=r"(u) : "f"(f));
    return u;
}
__device__ __forceinline__ void cp16(uint32_t* dst, const uint32_t* src) {
    unsigned sa = (unsigned)__cvta_generic_to_shared(dst);
    asm volatile("cp.async.cg.shared.global [%0], [%1], 16;" :: "r"(sa), "l"(src));
}
__device__ __forceinline__ void ldsm_x4(uint32_t* r, uint32_t saddr) {
    asm volatile("ldmatrix.sync.aligned.m8n8.x4.shared.b16 {%0,%1,%2,%3}, [%4];"
        : "=r"(r[0]), "=r"(r[1]), "=r"(r[2]), "=r"(r[3]) : "r"(saddr));
}
__device__ __forceinline__ void ldsm_x2(uint32_t* r, uint32_t saddr) {
    asm volatile("ldmatrix.sync.aligned.m8n8.x2.shared.b16 {%0,%1}, [%2];"
        : "=r"(r[0]), "=r"(r[1]) : "r"(saddr));
}
__device__ __forceinline__ unsigned atom_add_acqrel(unsigned* p, unsigned v) {
    unsigned old;
    asm volatile("atom.add.acq_rel.gpu.u32 %0, [%1], %2;"
        : "=r"(old) : "l"(p), "r"(v) : "memory");
    return old;
}
__device__ __forceinline__ unsigned ld_acquire(const unsigned* p) {
    unsigned v;
    asm volatile("ld.acquire.gpu.u32 %0, [%1];" : "=r"(v) : "l"(p) : "memory");
    return v;
}

// Split-barrier primitives over the 8 CTAs of one m-tile group.
__device__ __forceinline__ void group_arrive(unsigned* cnt) {
    __syncthreads();
    if (threadIdx.x == 0) atom_add_acqrel(cnt, 1u);
}
__device__ __forceinline__ void group_wait(unsigned* cnt, unsigned target) {
    __syncthreads();
    if (threadIdx.x == 0) {
        while (ld_acquire(cnt) < target) __nanosleep(32);
    }
    __syncthreads();
}

// Full rendezvous — once at kernel end to reset epoch counters for graph replay.
__device__ __forceinline__ void group_rendezvous(int grp) {
    __syncthreads();
    if (threadIdx.x == 0) {
        unsigned* cnt = &g_gc[grp * 32];
        unsigned* gen = &g_gg[grp * 32];
        unsigned g = ld_acquire(gen);
        unsigned old = atom_add_acqrel(cnt, 1u);
        if (old == GRPSZ - 1u) {
            atom_add_acqrel(cnt, (unsigned)(-GRPSZ));
            atom_add_acqrel(gen, 1u);
        } else {
            while (ld_acquire(gen) == g) __nanosleep(32);
        }
    }
    __syncthreads();
}

// ---------- prep kernels ----------
__global__ void prep_weights(const float* __restrict__ W0, const float* __restrict__ W1,
                             const float* __restrict__ W2, const float* __restrict__ W3) {
    int idx = blockIdx.x * blockDim.x + threadIdx.x;
    if (idx >= 4 * WSTEP) return;
    int mat = idx / WSTEP;
    int rem = idx - mat * WSTEP;
    int n = rem / HU32;
    int k = rem - n * HU32;
    const float* W = (mat == 0) ? W0 : (mat == 1) ? W1 : (mat == 2) ? W2 : W3;
    int gate = n & 3, h = n >> 2;
    float v = 0.f;
    if (h < HDIM && k < HDIM)
        v = W[(size_t)(gate * HDIM + h) * HDIM + k];
    g_WT[idx] = f2tf32(v);
}

__global__ void prep_z(const float* __restrict__ z) {
    int idx = blockIdx.x * blockDim.x + threadIdx.x;
    if (idx >= ASTRIDE) return;
    int r = idx / HU32;
    int k = idx - r * HU32;
    float v = (k < HDIM) ? z[(size_t)r * HDIM + k] : 0.f;
    g_zT[idx] = f2tf32(v);
}

// ---------- staging ----------
__device__ __forceinline__ void stage_A(
    uint32_t* sbuf, const uint32_t* __restrict__ aT, int mBase, int p0, int tid)
{
#pragma unroll
    for (int i = 0; i < 4; i++) {
        int s = tid + i * NTHREADS;              // 0..1023
        int r = s >> 3;                          // 0..127 (8 quads/row)
        int q = s & 7;
        cp16(sbuf + r * SMS + q * 4, aT + (size_t)(mBase + r) * HU32 + p0 + q * 4);
    }
}
__device__ __forceinline__ void stage_B(
    uint32_t* sbuf, const uint32_t* __restrict__ bT, int nBase, int p0, int tid)
{
#pragma unroll
    for (int i = 0; i < 5; i++) {
        int s = tid + i * NTHREADS;              // 0..1279
        int r = s >> 3;                          // 0..159
        int q = s & 7;
        cp16(sbuf + A_U32 + r * SMS + q * 4, bT + (size_t)(nBase + r) * HU32 + p0 + q * 4);
    }
}

#define MMATF(ACC, AR, BR)                                                       \
    asm volatile("mma.sync.aligned.m16n8k8.row.col.f32.tf32.tf32.f32 "           \
        "{%0,%1,%2,%3}, {%4,%5,%6,%7}, {%8,%9}, {%0,%1,%2,%3};\n"                \
        : "+f"(ACC[0]), "+f"(ACC[1]), "+f"(ACC[2]), "+f"(ACC[3])                 \
        : "r"(AR[0]), "r"(AR[1]), "r"(AR[2]), "r"(AR[3]),                        \
          "r"(BR[0]), "r"(BR[1]));

// Plain-TF32 tile: 4 k8 slabs x (4 mi x 5 ni) = 80 MMAs (vs 120 for bf16x3).
// ldmatrix addressing identical in form to the bf16 kernel (8x8 b16 tile ==
// 8x4 tf32 tile); SMS=36 keeps all ldmatrix phases bank-conflict-free.
__device__ __forceinline__ void mma_tile(
    uint32_t sbase, float (*acc)[5][4], int warpM, int warpN, int lane)
{
    const uint32_t AsT = sbase;
    const uint32_t BsT = sbase + A_U32 * 4;
    const int aRow = lane & 15;
    const int aK4  = (lane & 16) >> 2;          // 0 or 4 (u32 units)
    const int bRow = (lane & 7) | ((lane & 16) >> 1);
    const int bK4  = (lane & 8) >> 1;           // 0 or 4
    const int bRow2 = lane & 7;                  // for x2 (lanes 0-15 used)
#pragma unroll
    for (int s4 = 0; s4 < 4; s4++) {
        const int ks = s4 * 8;
        uint32_t b[5][2];
#pragma unroll
        for (int np = 0; np < 2; np++) {         // ni pairs (0,1) and (2,3)
            int nb = warpN * 40 + np * 16;
            uint32_t r4[4];
            ldsm_x4(r4, BsT + (uint32_t)(((nb + bRow) * SMS + ks + bK4) << 2));
            b[2 * np][0] = r4[0]; b[2 * np][1] = r4[1];
            b[2 * np + 1][0] = r4[2]; b[2 * np + 1][1] = r4[3];
        }
        {
            int nb = warpN * 40 + 32;            // ni = 4
            ldsm_x2(b[4], BsT + (uint32_t)(((nb + bRow2) * SMS + ks + bK4) << 2));
        }
#pragma unroll
        for (int mi = 0; mi < 4; mi++) {
            int rb = warpM * 64 + mi * 16;
            uint32_t a[4];
            ldsm_x4(a, AsT + (uint32_t)(((rb + aRow) * SMS + ks + aK4) << 2));
#pragma unroll
            for (int ni = 0; ni < 5; ni++) {
                MMATF(acc[mi][ni], a, b[ni]);
            }
        }
    }
}

// One fused LSTM cell: single 20-tile pipeline (recurrent tiles 0-9, input
// tiles 10-19), group wait embedded in tile-10's staging slot, tail prefetch
// of the NEXT cell's tile 0 covered by the epilogue.
__device__ void run_cell(
    uint32_t smbase,
    const uint32_t* __restrict__ rT,   // recurrent A (null at t=0)
    const uint32_t* __restrict__ WrT,
    const uint32_t* __restrict__ xT,   // input A
    const uint32_t* __restrict__ WxT,
    unsigned* waitCnt, unsigned waitTarget,
    const float* __restrict__ cprev, const float* bias_s,
    uint32_t* __restrict__ hpT,        // tf32 h out
    float* __restrict__ houtF, int hOutStride,
    float* __restrict__ cout,
    int mBase, int hb,
    const uint32_t* __restrict__ nxAT, // next-cell tile0 A (or null)
    const uint32_t* __restrict__ nxBT) // next-cell tile0 B (or null)
{
    const int tid   = threadIdx.x;
    const int lane  = tid & 31;
    const int warp  = tid >> 5;
    const int warpM = warp >> 2;
    const int warpN = warp & 3;
    const int gId   = lane >> 2;
    const int tid4  = lane & 3;
    const int nBase = hb * 4;

    float acc[4][5][4];
#pragma unroll
    for (int a = 0; a < 4; a++)
#pragma unroll
        for (int b = 0; b < 5; b++)
#pragma unroll
            for (int c = 0; c < 4; c++) acc[a][b][c] = 0.f;

    const int kStart = rT ? 0 : NKT;

    if (!rT) {
        // t=0 cells: wait then stage input tile0 A (B pre-staged in buf0)
        group_wait(waitCnt, waitTarget);
        stage_A(dynsmem, xT, mBase, 0, tid);
        asm volatile("cp.async.commit_group;");
    }

#pragma unroll 1
    for (int kt = kStart; kt < 2 * NKT; kt++) {
        asm volatile("cp.async.wait_group 0;");
        __syncthreads();
        int k2 = kt + 1;
        if (k2 < 2 * NKT) {
            if (k2 == NKT) group_wait(waitCnt, waitTarget);  // seg boundary
            const uint32_t *sAT, *sBT;
            int p0;
            if (k2 < NKT) { sAT = rT; sBT = WrT; p0 = k2 * BK; }
            else          { sAT = xT; sBT = WxT; p0 = (k2 - NKT) * BK; }
            uint32_t* buf = dynsmem + (size_t)(k2 & 1) * BUFU32;
            stage_A(buf, sAT, mBase, p0, tid);
            stage_B(buf, sBT, nBase, p0, tid);
            asm volatile("cp.async.commit_group;");
        } else {
            int any = 0;
            if (nxBT) { stage_B(dynsmem, nxBT, nBase, 0, tid); any = 1; }
            if (nxAT) { stage_A(dynsmem, nxAT, mBase, 0, tid); any = 1; }
            if (any) asm volatile("cp.async.commit_group;");
        }
        mma_tile(smbase + (uint32_t)((kt & 1) * BUFU32 * 4), acc, warpM, warpN, lane);
    }

    // epilogue: assemble i,f,g,o per hidden unit via shfl_xor(1); fast-math gates
#pragma unroll
    for (int mi = 0; mi < 4; mi++) {
        const int row_r = mBase + warpM * 64 + mi * 16 + gId;
#pragma unroll
        for (int ni = 0; ni < 5; ni++) {
            float c0v = acc[mi][ni][0], c1v = acc[mi][ni][1];
            float c2v = acc[mi][ni][2], c3v = acc[mi][ni][3];
            float p0 = __shfl_xor_sync(0xffffffffu, c0v, 1);
            float p1 = __shfl_xor_sync(0xffffffffu, c1v, 1);
            float p2 = __shfl_xor_sync(0xffffffffu, c2v, 1);
            float p3 = __shfl_xor_sync(0xffffffffu, c3v, 1);

            const int hl = warpN * 10 + ni * 2 + (tid4 >> 1);
            const int h = hb + hl;
            float iraw, fraw, graw, oraw;
            int row;
            if ((tid4 & 1) == 0) {
                iraw = c0v; fraw = c1v; graw = p0; oraw = p1; row = row_r;
            } else {
                iraw = p2; fraw = p3; graw = c2v; oraw = c3v; row = row_r + 8;
            }
            if (h < HDIM) {
                iraw += bias_s[4 * hl + 0];
                fraw += bias_s[4 * hl + 1];
                graw += bias_s[4 * hl + 2];
                oraw += bias_s[4 * hl + 3];
                float ig = __fdividef(1.f, 1.f + __expf(-iraw));
                float fg = __fdividef(1.f, 1.f + __expf(-fraw));
                float gg = 1.f - __fdividef(2.f, __expf(2.f * graw) + 1.f);
                float og = __fdividef(1.f, 1.f + __expf(-oraw));
                float cp = cprev ? cprev[(size_t)row * HDIM + h] : 0.f;
                float cn = fg * cp + ig * gg;
                float hn = og * (1.f - __fdividef(2.f, __expf(2.f * cn) + 1.f));
                cout[(size_t)row * HDIM + h] = cn;
                hpT[(size_t)row * HPAD + h] = f2tf32(hn);
                if (houtF) houtF[(size_t)row * hOutStride + h] = hn;
            }
        }
    }
}

// ---------- persistent driver kernel ----------
__global__ __launch_bounds__(NTHREADS, 2) void lstm_persistent(
    const float* __restrict__ b_ih0, const float* __restrict__ b_hh0,
    const float* __restrict__ b_ih1, const float* __restrict__ b_hh1,
    float* __restrict__ out, int T)
{
    const int bid   = blockIdx.x;
    const int mBase = (bid >> 3) * BM;   // 32 m-tiles
    const int hb    = (bid & 7) * BH;    // 8 h-blocks
    const int grp   = bid >> 3;          // sync group = m-tile
    const int tid   = threadIdx.x;
    const int nBase = hb * 4;

    const uint32_t smbase = (uint32_t)__cvta_generic_to_shared(dynsmem);
    unsigned* cntA = &g_cntA[grp * 32];
    unsigned* cntB = &g_cntB[grp * 32];

    float* bias0 = (float*)(dynsmem + 2 * BUFU32);
    float* bias1 = bias0 + BNC;
    if (tid < BNC) {
        int gate = tid & 3, hl = tid >> 2, h = hb + hl;
        bias0[tid] = (h < HDIM) ? (b_ih0[gate * HDIM + h] + b_hh0[gate * HDIM + h]) : 0.f;
        bias1[tid] = (h < HDIM) ? (b_ih1[gate * HDIM + h] + b_hh1[gate * HDIM + h]) : 0.f;
    }
    __syncthreads();

    // prologue prefetch: L0[0]'s first tile is the input segment (z, Wih0)
    stage_B(dynsmem, g_WT + 0 * WSTEP, nBase, 0, tid);
    asm volatile("cp.async.commit_group;");

#pragma unroll 1
    for (int t = 0; t < T; t++) {
        const int wr = t & 1, rd = (t + 1) & 1;

        // ---- layer 0 ----
        if (t == 0) {
            run_cell(smbase,
                     nullptr, nullptr,
                     g_zT, g_WT + 0 * WSTEP,
                     cntA, 0u,
                     nullptr, bias0,
                     g_h0T, nullptr, 0, g_c0, mBase, hb,
                     nullptr, g_WT + 2 * WSTEP);
        } else {
            run_cell(smbase,
                     g_h0T + (size_t)rd * ASTRIDE, g_WT + 1 * WSTEP,
                     g_oT + (size_t)rd * ASTRIDE, g_WT + 0 * WSTEP,
                     cntA, 8u * (unsigned)t,
                     g_c0, bias0,
                     g_h0T + (size_t)wr * ASTRIDE, nullptr, 0, g_c0, mBase, hb,
                     g_oT + (size_t)rd * ASTRIDE, g_WT + 3 * WSTEP);
        }
        group_arrive(cntB);            // h0[t] published

        // ---- layer 1 (writes fp32 h into output slice t) ----
        if (t == 0) {
            run_cell(smbase,
                     nullptr, nullptr,
                     g_h0T, g_WT + 2 * WSTEP,
                     cntB, 8u,
                     nullptr, bias1,
                     g_oT, out, T * HDIM, g_c1, mBase, hb,
                     g_h0T, g_WT + 1 * WSTEP);
        } else {
            const int last = (t + 1 >= T);
            run_cell(smbase,
                     g_oT + (size_t)rd * ASTRIDE, g_WT + 3 * WSTEP,
                     g_h0T + (size_t)wr * ASTRIDE, g_WT + 2 * WSTEP,
                     cntB, 8u * (unsigned)(t + 1),
                     g_c1, bias1,
                     g_oT + (size_t)wr * ASTRIDE,
                     out + (size_t)t * HDIM, T * HDIM, g_c1, mBase, hb,
                     last ? nullptr : g_h0T + (size_t)wr * ASTRIDE,
                     last ? nullptr : g_WT + 1 * WSTEP);
        }
        group_arrive(cntA);            // o[t] published
    }

    // reset epoch counters for graph replay
    group_rendezvous(grp);
    if ((bid & 7) == 0 && tid == 0) {
        atom_add_acqrel(cntA, (unsigned)(-(8u * (unsigned)T)));
        atom_add_acqrel(cntB, (unsigned)(-(8u * (unsigned)T)));
    }
}

extern "C" void kernel_launch(void* const* d_in, const int* in_sizes, int n_in,
                              void* d_out, int out_size)
{
    const float* z     = (const float*)d_in[0];
    const float* W_ih0 = (const float*)d_in[1];
    const float* W_hh0 = (const float*)d_in[2];
    const float* b_ih0 = (const float*)d_in[3];
    const float* b_hh0 = (const float*)d_in[4];
    const float* W_ih1 = (const float*)d_in[5];
    const float* W_hh1 = (const float*)d_in[6];
    const float* b_ih1 = (const float*)d_in[7];
    const float* b_hh1 = (const float*)d_in[8];
    float* out = (float*)d_out;

    const int Bsz = in_sizes[0] / HDIM;      // 4096
    const int T   = out_size / (Bsz * HDIM); // 64

    prep_weights<<<(4 * WSTEP + 255) / 256, 256>>>(W_ih0, W_hh0, W_ih1, W_hh1);
    prep_z<<<(ASTRIDE + 255) / 256, 256>>>(z);

    static int attr_done = 0;
    if (!attr_done) {
        cudaFuncSetAttribute(lstm_persistent,
                             cudaFuncAttributeMaxDynamicSharedMemorySize,
                             SMEM_U32 * 4);
        attr_done = 1;
    }
    lstm_persistent<<<NGRP * GRPSZ, NTHREADS, SMEM_U32 * 4>>>(b_ih0, b_hh0, b_ih1, b_hh1,
                                                              out, T);
}

// round 16
// speedup vs baseline: 2.3502x; 1.0829x over previous
#include <cuda_runtime.h>
#include <cuda_fp16.h>
#include <cstdint>

// ---- problem constants ----
#define HDIM 300
#define HPAD 320          // padded k extent (fp16 elems)
#define HPAIR 160         // u32 (fp16x2) per activation/weight row
#define BROWS 4096
#define BM 128            // batch rows per CTA
#define BH 40             // hidden units per CTA -> 8 h-blocks
#define BNC 160           // gate-columns per CTA (4*BH)
#define BK 32             // k elements per tile
#define KPAIR 16          // u32 per row per tile
#define SMS 20            // smem row stride in u32 (16 + 4 pad) -> ldmatrix conflict-free
#define NKT 10            // k-tiles per GEMM segment
#define NTHREADS 256
#define NW 1280           // padded row-permuted weight rows
#define PAIRSZ (BROWS * HPAIR)
#define WSTEP (NW * HPAIR)
#define NGRP 32           // one independent sync group per m-tile
#define GRPSZ 8           // 8 h-block CTAs per group
// dynamic smem layout (u32 units)
#define A_U32 2560        // 128 * 20
#define BUFU32 5760       // A(2560) + B(160*20=3200)
#define SMEM_U32 (2 * BUFU32 + 2 * BNC)

// ---- device scratch (no allocation allowed) ----
__device__ uint32_t g_zP[PAIRSZ];
__device__ uint32_t g_h0P[2 * PAIRSZ];        // ping-pong layer0 h (fp16 pairs)
__device__ uint32_t g_oP[2 * PAIRSZ];         // ping-pong layer1 h
__device__ uint32_t g_WP[4 * WSTEP];          // Wih0,Whh0,Wih1,Whh1 (row-permuted fp16)
__device__ float g_c0[BROWS * HDIM], g_c1[BROWS * HDIM];
__device__ unsigned g_cntA[NGRP * 32];        // arrive/wait epoch counters (line-padded)
__device__ unsigned g_cntB[NGRP * 32];
__device__ unsigned g_gc[NGRP * 32];          // rendezvous for end-of-launch reset
__device__ unsigned g_gg[NGRP * 32];

extern __shared__ uint32_t dynsmem[];

// ---------- helpers ----------
__device__ __forceinline__ uint32_t packh2(float v0, float v1) {
    __half h0 = __float2half_rn(v0);
    __half h1 = __float2half_rn(v1);
    return (uint32_t)__half_as_ushort(h0) | ((uint32_t)__half_as_ushort(h1) << 16);
}
__device__ __forceinline__ void cp16(uint32_t* dst, const uint32_t* src) {
    unsigned sa = (unsigned)__cvta_generic_to_shared(dst);
    asm volatile("cp.async.cg.shared.global [%0], [%1], 16;" :: "r"(sa), "l"(src));
}
__device__ __forceinline__ void ldsm_x4(uint32_t* r, uint32_t saddr) {
    asm volatile("ldmatrix.sync.aligned.m8n8.x4.shared.b16 {%0,%1,%2,%3}, [%4];"
        : "=r"(r[0]), "=r"(r[1]), "=r"(r[2]), "=r"(r[3]) : "r"(saddr));
}
__device__ __forceinline__ void ldsm_x2(uint32_t* r, uint32_t saddr) {
    asm volatile("ldmatrix.sync.aligned.m8n8.x2.shared.b16 {%0,%1}, [%2];"
        : "=r"(r[0]), "=r"(r[1]) : "r"(saddr));
}
__device__ __forceinline__ unsigned atom_add_acqrel(unsigned* p, unsigned v) {
    unsigned old;
    asm volatile("atom.add.acq_rel.gpu.u32 %0, [%1], %2;"
        : "=r"(old) : "l"(p), "r"(v) : "memory");
    return old;
}
__device__ __forceinline__ unsigned ld_acquire(const unsigned* p) {
    unsigned v;
    asm volatile("ld.acquire.gpu.u32 %0, [%1];" : "=r"(v) : "l"(p) : "memory");
    return v;
}

// Split-barrier primitives over the 8 CTAs of one m-tile group.
__device__ __forceinline__ void group_arrive(unsigned* cnt) {
    __syncthreads();
    if (threadIdx.x == 0) atom_add_acqrel(cnt, 1u);
}
__device__ __forceinline__ void group_wait(unsigned* cnt, unsigned target) {
    __syncthreads();
    if (threadIdx.x == 0) {
        while (ld_acquire(cnt) < target) __nanosleep(32);
    }
    __syncthreads();
}

// Full rendezvous — once at kernel end to reset epoch counters for graph replay.
__device__ __forceinline__ void group_rendezvous(int grp) {
    __syncthreads();
    if (threadIdx.x == 0) {
        unsigned* cnt = &g_gc[grp * 32];
        unsigned* gen = &g_gg[grp * 32];
        unsigned g = ld_acquire(gen);
        unsigned old = atom_add_acqrel(cnt, 1u);
        if (old == GRPSZ - 1u) {
            atom_add_acqrel(cnt, (unsigned)(-GRPSZ));
            atom_add_acqrel(gen, 1u);
        } else {
            while (ld_acquire(gen) == g) __nanosleep(32);
        }
    }
    __syncthreads();
}

// ---------- prep kernels ----------
__global__ void prep_weights(const float* __restrict__ W0, const float* __restrict__ W1,
                             const float* __restrict__ W2, const float* __restrict__ W3) {
    int idx = blockIdx.x * blockDim.x + threadIdx.x;
    if (idx >= 4 * WSTEP) return;
    int mat = idx / WSTEP;
    int rem = idx - mat * WSTEP;
    int n = rem / HPAIR;
    int p = rem - n * HPAIR;
    const float* W = (mat == 0) ? W0 : (mat == 1) ? W1 : (mat == 2) ? W2 : W3;
    int gate = n & 3, h = n >> 2;
    int k = p * 2;
    float v0 = 0.f, v1 = 0.f;
    if (h < HDIM) {
        const float* row = W + (size_t)(gate * HDIM + h) * HDIM;
        if (k < HDIM)     v0 = row[k];
        if (k + 1 < HDIM) v1 = row[k + 1];
    }
    g_WP[idx] = packh2(v0, v1);
}

__global__ void prep_z(const float* __restrict__ z) {
    int idx = blockIdx.x * blockDim.x + threadIdx.x;
    if (idx >= PAIRSZ) return;
    int r = idx / HPAIR;
    int p = idx - r * HPAIR;
    int k = p * 2;
    float v0 = (k < HDIM) ? z[(size_t)r * HDIM + k] : 0.f;
    float v1 = (k + 1 < HDIM) ? z[(size_t)r * HDIM + k + 1] : 0.f;
    g_zP[idx] = packh2(v0, v1);
}

// ---------- staging ----------
__device__ __forceinline__ void stage_A(
    uint32_t* sbuf, const uint32_t* __restrict__ aP, int mBase, int p0, int tid)
{
#pragma unroll
    for (int i = 0; i < 2; i++) {
        int s = tid + i * NTHREADS;              // 0..511
        int r = s >> 2;                          // 0..127 (4 quads/row)
        int q = s & 3;
        cp16(sbuf + r * SMS + q * 4, aP + (size_t)(mBase + r) * HPAIR + p0 + q * 4);
    }
}
__device__ __forceinline__ void stage_B(
    uint32_t* sbuf, const uint32_t* __restrict__ bP, int nBase, int p0, int tid)
{
#pragma unroll
    for (int i = 0; i < 3; i++) {
        int s = tid + i * NTHREADS;              // 0..767 (640 used)
        if (s < 640) {
            int r = s >> 2;                      // 0..159
            int q = s & 3;
            cp16(sbuf + A_U32 + r * SMS + q * 4, bP + (size_t)(nBase + r) * HPAIR + p0 + q * 4);
        }
    }
}

#define MMAH(ACC, AR, BR)                                                        \
    asm volatile("mma.sync.aligned.m16n8k16.row.col.f32.f16.f16.f32 "            \
        "{%0,%1,%2,%3}, {%4,%5,%6,%7}, {%8,%9}, {%0,%1,%2,%3};\n"                \
        : "+f"(ACC[0]), "+f"(ACC[1]), "+f"(ACC[2]), "+f"(ACC[3])                 \
        : "r"(AR[0]), "r"(AR[1]), "r"(AR[2]), "r"(AR[3]),                        \
          "r"(BR[0]), "r"(BR[1]));

// FP16 k16 tile: 2 kk slabs x (4 mi x 5 ni) = 40 MMAs (vs 80 tf32 / 120 bf16x3).
// ldmatrix addressing identical to the validated R14 b16 layout; SMS=20 keeps
// all ldmatrix phases bank-conflict-free.
__device__ __forceinline__ void mma_tile(
    uint32_t sbase, float (*acc)[5][4], int warpM, int warpN, int lane)
{
    const uint32_t AsP = sbase;
    const uint32_t BsP = sbase + A_U32 * 4;
    const int aRow = lane & 15;
    const int aK4  = (lane & 16) >> 2;          // 0 or 4 (u32 units)
    const int bRow = (lane & 7) | ((lane & 16) >> 1);
    const int bK4  = (lane & 8) >> 1;           // 0 or 4
    const int bRow2 = lane & 7;                  // for x2 (lanes 0-15 used)
#pragma unroll
    for (int kk = 0; kk < 2; kk++) {
        const int ko2 = kk * 8;
        uint32_t b[5][2];
#pragma unroll
        for (int np = 0; np < 2; np++) {         // ni pairs (0,1) and (2,3)
            int nb = warpN * 40 + np * 16;
            uint32_t r4[4];
            ldsm_x4(r4, BsP + (uint32_t)(((nb + bRow) * SMS + ko2 + bK4) << 2));
            b[2 * np][0] = r4[0]; b[2 * np][1] = r4[1];
            b[2 * np + 1][0] = r4[2]; b[2 * np + 1][1] = r4[3];
        }
        {
            int nb = warpN * 40 + 32;            // ni = 4
            ldsm_x2(b[4], BsP + (uint32_t)(((nb + bRow2) * SMS + ko2 + bK4) << 2));
        }
#pragma unroll
        for (int mi = 0; mi < 4; mi++) {
            int rb = warpM * 64 + mi * 16;
            uint32_t a[4];
            ldsm_x4(a, AsP + (uint32_t)(((rb + aRow) * SMS + ko2 + aK4) << 2));
#pragma unroll
            for (int ni = 0; ni < 5; ni++) {
                MMAH(acc[mi][ni], a, b[ni]);
            }
        }
    }
}

// One fused LSTM cell: single 20-tile pipeline (recurrent tiles 0-9, input
// tiles 10-19), group wait embedded in tile-10's staging slot, tail prefetch
// of the NEXT cell's tile 0 covered by the epilogue.
__device__ void run_cell(
    uint32_t smbase,
    const uint32_t* __restrict__ rP,   // recurrent A (null at t=0)
    const uint32_t* __restrict__ WrP,
    const uint32_t* __restrict__ xP,   // input A
    const uint32_t* __restrict__ WxP,
    unsigned* waitCnt, unsigned waitTarget,
    const float* __restrict__ cprev, const float* bias_s,
    uint32_t* __restrict__ hpP,        // fp16-pair h out
    float* __restrict__ houtF, int hOutStride,
    float* __restrict__ cout,
    int mBase, int hb,
    const uint32_t* __restrict__ nxAP, // next-cell tile0 A (or null)
    const uint32_t* __restrict__ nxBP) // next-cell tile0 B (or null)
{
    const int tid   = threadIdx.x;
    const int lane  = tid & 31;
    const int warp  = tid >> 5;
    const int warpM = warp >> 2;
    const int warpN = warp & 3;
    const int gId   = lane >> 2;
    const int tid4  = lane & 3;
    const int nBase = hb * 4;

    float acc[4][5][4];
#pragma unroll
    for (int a = 0; a < 4; a++)
#pragma unroll
        for (int b = 0; b < 5; b++)
#pragma unroll
            for (int c = 0; c < 4; c++) acc[a][b][c] = 0.f;

    const int kStart = rP ? 0 : NKT;

    if (!rP) {
        // t=0 cells: wait then stage input tile0 A (B pre-staged in buf0)
        group_wait(waitCnt, waitTarget);
        stage_A(dynsmem, xP, mBase, 0, tid);
        asm volatile("cp.async.commit_group;");
    }

#pragma unroll 1
    for (int kt = kStart; kt < 2 * NKT; kt++) {
        asm volatile("cp.async.wait_group 0;");
        __syncthreads();
        int k2 = kt + 1;
        if (k2 < 2 * NKT) {
            if (k2 == NKT) group_wait(waitCnt, waitTarget);  // seg boundary
            const uint32_t *sAP, *sBP;
            int p0;
            if (k2 < NKT) { sAP = rP; sBP = WrP; p0 = k2 * KPAIR; }
            else          { sAP = xP; sBP = WxP; p0 = (k2 - NKT) * KPAIR; }
            uint32_t* buf = dynsmem + (size_t)(k2 & 1) * BUFU32;
            stage_A(buf, sAP, mBase, p0, tid);
            stage_B(buf, sBP, nBase, p0, tid);
            asm volatile("cp.async.commit_group;");
        } else {
            int any = 0;
            if (nxBP) { stage_B(dynsmem, nxBP, nBase, 0, tid); any = 1; }
            if (nxAP) { stage_A(dynsmem, nxAP, mBase, 0, tid); any = 1; }
            if (any) asm volatile("cp.async.commit_group;");
        }
        mma_tile(smbase + (uint32_t)((kt & 1) * BUFU32 * 4), acc, warpM, warpN, lane);
    }

    // epilogue: assemble i,f,g,o per hidden unit via shfl_xor(1); fast-math gates
    __half* hp16 = (__half*)hpP;
#pragma unroll
    for (int mi = 0; mi < 4; mi++) {
        const int row_r = mBase + warpM * 64 + mi * 16 + gId;
#pragma unroll
        for (int ni = 0; ni < 5; ni++) {
            float c0v = acc[mi][ni][0], c1v = acc[mi][ni][1];
            float c2v = acc[mi][ni][2], c3v = acc[mi][ni][3];
            float p0 = __shfl_xor_sync(0xffffffffu, c0v, 1);
            float p1 = __shfl_xor_sync(0xffffffffu, c1v, 1);
            float p2 = __shfl_xor_sync(0xffffffffu, c2v, 1);
            float p3 = __shfl_xor_sync(0xffffffffu, c3v, 1);

            const int hl = warpN * 10 + ni * 2 + (tid4 >> 1);
            const int h = hb + hl;
            float iraw, fraw, graw, oraw;
            int row;
            if ((tid4 & 1) == 0) {
                iraw = c0v; fraw = c1v; graw = p0; oraw = p1; row = row_r;
            } else {
                iraw = p2; fraw = p3; graw = c2v; oraw = c3v; row = row_r + 8;
            }
            if (h < HDIM) {
                iraw += bias_s[4 * hl + 0];
                fraw += bias_s[4 * hl + 1];
                graw += bias_s[4 * hl + 2];
                oraw += bias_s[4 * hl + 3];
                float ig = __fdividef(1.f, 1.f + __expf(-iraw));
                float fg = __fdividef(1.f, 1.f + __expf(-fraw));
                float gg = 1.f - __fdividef(2.f, __expf(2.f * graw) + 1.f);
                float og = __fdividef(1.f, 1.f + __expf(-oraw));
                float cp = cprev ? cprev[(size_t)row * HDIM + h] : 0.f;
                float cn = fg * cp + ig * gg;
                float hn = og * (1.f - __fdividef(2.f, __expf(2.f * cn) + 1.f));
                cout[(size_t)row * HDIM + h] = cn;
                hp16[(size_t)row * HPAD + h] = __float2half_rn(hn);
                if (houtF) houtF[(size_t)row * hOutStride + h] = hn;
            }
        }
    }
}

// ---------- persistent driver kernel ----------
__global__ __launch_bounds__(NTHREADS, 2) void lstm_persistent(
    const float* __restrict__ b_ih0, const float* __restrict__ b_hh0,
    const float* __restrict__ b_ih1, const float* __restrict__ b_hh1,
    float* __restrict__ out, int T)
{
    const int bid   = blockIdx.x;
    const int mBase = (bid >> 3) * BM;   // 32 m-tiles
    const int hb    = (bid & 7) * BH;    // 8 h-blocks
    const int grp   = bid >> 3;          // sync group = m-tile
    const int tid   = threadIdx.x;
    const int nBase = hb * 4;

    const uint32_t smbase = (uint32_t)__cvta_generic_to_shared(dynsmem);
    unsigned* cntA = &g_cntA[grp * 32];
    unsigned* cntB = &g_cntB[grp * 32];

    float* bias0 = (float*)(dynsmem + 2 * BUFU32);
    float* bias1 = bias0 + BNC;
    if (tid < BNC) {
        int gate = tid & 3, hl = tid >> 2, h = hb + hl;
        bias0[tid] = (h < HDIM) ? (b_ih0[gate * HDIM + h] + b_hh0[gate * HDIM + h]) : 0.f;
        bias1[tid] = (h < HDIM) ? (b_ih1[gate * HDIM + h] + b_hh1[gate * HDIM + h]) : 0.f;
    }
    __syncthreads();

    // prologue prefetch: L0[0]'s first tile is the input segment (z, Wih0)
    stage_B(dynsmem, g_WP + 0 * WSTEP, nBase, 0, tid);
    asm volatile("cp.async.commit_group;");

#pragma unroll 1
    for (int t = 0; t < T; t++) {
        const int wr = t & 1, rd = (t + 1) & 1;

        // ---- layer 0 ----
        if (t == 0) {
            run_cell(smbase,
                     nullptr, nullptr,
                     g_zP, g_WP + 0 * WSTEP,
                     cntA, 0u,
                     nullptr, bias0,
                     g_h0P, nullptr, 0, g_c0, mBase, hb,
                     nullptr, g_WP + 2 * WSTEP);
        } else {
            run_cell(smbase,
                     g_h0P + (size_t)rd * PAIRSZ, g_WP + 1 * WSTEP,
                     g_oP + (size_t)rd * PAIRSZ, g_WP + 0 * WSTEP,
                     cntA, 8u * (unsigned)t,
                     g_c0, bias0,
                     g_h0P + (size_t)wr * PAIRSZ, nullptr, 0, g_c0, mBase, hb,
                     g_oP + (size_t)rd * PAIRSZ, g_WP + 3 * WSTEP);
        }
        group_arrive(cntB);            // h0[t] published

        // ---- layer 1 (writes fp32 h into output slice t) ----
        if (t == 0) {
            run_cell(smbase,
                     nullptr, nullptr,
                     g_h0P, g_WP + 2 * WSTEP,
                     cntB, 8u,
                     nullptr, bias1,
                     g_oP, out, T * HDIM, g_c1, mBase, hb,
                     g_h0P, g_WP + 1 * WSTEP);
        } else {
            const int last = (t + 1 >= T);
            run_cell(smbase,
                     g_oP + (size_t)rd * PAIRSZ, g_WP + 3 * WSTEP,
                     g_h0P + (size_t)wr * PAIRSZ, g_WP + 2 * WSTEP,
                     cntB, 8u * (unsigned)(t + 1),
                     g_c1, bias1,
                     g_oP + (size_t)wr * PAIRSZ,
                     out + (size_t)t * HDIM, T * HDIM, g_c1, mBase, hb,
                     last ? nullptr : g_h0P + (size_t)wr * PAIRSZ,
                     last ? nullptr : g_WP + 1 * WSTEP);
        }
        group_arrive(cntA);            // o[t] published
    }

    // reset epoch counters for graph replay
    group_rendezvous(grp);
    if ((bid & 7) == 0 && tid == 0) {
        atom_add_acqrel(cntA, (unsigned)(-(8u * (unsigned)T)));
        atom_add_acqrel(cntB, (unsigned)(-(8u * (unsigned)T)));
    }
}

extern "C" void kernel_launch(void* const* d_in, const int* in_sizes, int n_in,
                              void* d_out, int out_size)
{
    const float* z     = (const float*)d_in[0];
    const float* W_ih0 = (const float*)d_in[1];
    const float* W_hh0 = (const float*)d_in[2];
    const float* b_ih0 = (const float*)d_in[3];
    const float* b_hh0 = (const float*)d_in[4];
    const float* W_ih1 = (const float*)d_in[5];
    const float* W_hh1 = (const float*)d_in[6];
    const float* b_ih1 = (const float*)d_in[7];
    const float* b_hh1 = (const float*)d_in[8];
    float* out = (float*)d_out;

    const int Bsz = in_sizes[0] / HDIM;      // 4096
    const int T   = out_size / (Bsz * HDIM); // 64

    prep_weights<<<(4 * WSTEP + 255) / 256, 256>>>(W_ih0, W_hh0, W_ih1, W_hh1);
    prep_z<<<(PAIRSZ + 255) / 256, 256>>>(z);

    static int attr_done = 0;
    if (!attr_done) {
        cudaFuncSetAttribute(lstm_persistent,
                             cudaFuncAttributeMaxDynamicSharedMemorySize,
                             SMEM_U32 * 4);
        attr_done = 1;
    }
    lstm_persistent<<<NGRP * GRPSZ, NTHREADS, SMEM_U32 * 4>>>(b_ih0, b_hh0, b_ih1, b_hh1,
                                                              out, T);
}